// round 9
// baseline (speedup 1.0000x reference)
#include <cuda_runtime.h>
#include <cuda_bf16.h>
#include <cstdint>

#define D_MODEL  1024
#define N_HEADS  16
#define HEAD_DIM 64
#define SEQ_L    2048
#define BATCH    4
#define WINDOW   512

#define MTOT (BATCH * SEQ_L)          // 8192

__device__ float g_q[MTOT * D_MODEL];
__device__ float g_k[MTOT * D_MODEL];
__device__ float g_v[MTOT * D_MODEL];
__device__ float g_att[MTOT * D_MODEL];
__device__ float g_xr[MTOT * D_MODEL];          // pre-rounded x
__device__ float g_wr[4 * D_MODEL * D_MODEL];   // pre-rounded Wq,Wk,Wv,Wo

__device__ __forceinline__ uint32_t f2tf32(float f) {
    uint32_t u;
    asm("cvt.rna.tf32.f32 %0, %1;" : "=r"(u) : "f"(f));
    return u;
}
__device__ __forceinline__ void mma_tf32(float* d, const uint32_t* a,
                                         uint32_t b0, uint32_t b1) {
    asm volatile(
        "mma.sync.aligned.m16n8k8.row.col.f32.tf32.tf32.f32 "
        "{%0,%1,%2,%3}, {%4,%5,%6,%7}, {%8,%9}, {%0,%1,%2,%3};"
        : "+f"(d[0]), "+f"(d[1]), "+f"(d[2]), "+f"(d[3])
        : "r"(a[0]), "r"(a[1]), "r"(a[2]), "r"(a[3]), "r"(b0), "r"(b1));
}
__device__ __forceinline__ void mma_bf16(float* d, const uint32_t* a,
                                         uint32_t b0, uint32_t b1) {
    asm volatile(
        "mma.sync.aligned.m16n8k16.row.col.f32.bf16.bf16.f32 "
        "{%0,%1,%2,%3}, {%4,%5,%6,%7}, {%8,%9}, {%0,%1,%2,%3};"
        : "+f"(d[0]), "+f"(d[1]), "+f"(d[2]), "+f"(d[3])
        : "r"(a[0]), "r"(a[1]), "r"(a[2]), "r"(a[3]), "r"(b0), "r"(b1));
}
__device__ __forceinline__ uint32_t smem_u32(const void* p) {
    uint32_t a;
    asm("{ .reg .u64 t; cvta.to.shared.u64 t, %1; cvt.u32.u64 %0, t; }"
        : "=r"(a) : "l"(p));
    return a;
}
__device__ __forceinline__ void ldsm_x4(uint32_t addr, uint32_t* r) {
    asm volatile(
        "ldmatrix.sync.aligned.m8n8.x4.shared.b16 {%0,%1,%2,%3}, [%4];"
        : "=r"(r[0]), "=r"(r[1]), "=r"(r[2]), "=r"(r[3]) : "r"(addr));
}
__device__ __forceinline__ void ldsm_x4_t(uint32_t addr, uint32_t* r) {
    asm volatile(
        "ldmatrix.sync.aligned.m8n8.x4.trans.shared.b16 {%0,%1,%2,%3}, [%4];"
        : "=r"(r[0]), "=r"(r[1]), "=r"(r[2]), "=r"(r[3]) : "r"(addr));
}
__device__ __forceinline__ void split_pair(float e0, float e1,
                                           uint32_t& h, uint32_t& l) {
    __nv_bfloat16 b0 = __float2bfloat16_rn(e0), b1 = __float2bfloat16_rn(e1);
    h = ((uint32_t)__bfloat16_as_ushort(b1) << 16) | __bfloat16_as_ushort(b0);
    float r0 = e0 - __bfloat162float(b0), r1 = e1 - __bfloat162float(b1);
    __nv_bfloat16 c0 = __float2bfloat16_rn(r0), c1 = __float2bfloat16_rn(r1);
    l = ((uint32_t)__bfloat16_as_ushort(c1) << 16) | __bfloat16_as_ushort(c0);
}

#define CP_ASYNC16(dst, src) \
    asm volatile("cp.async.cg.shared.global [%0], [%1], 16;" \
                 :: "r"(dst), "l"(src))
#define CP_COMMIT() asm volatile("cp.async.commit_group;")
#define CP_WAIT1()  asm volatile("cp.async.wait_group 1;" ::: "memory")

// ---------------------------------------------------------------------------
// Merged pre-round pass: y=0 -> x (xn4), y=1..4 -> Wq/Wk/Wv/Wo (wn4 each).
// ---------------------------------------------------------------------------
__global__ void round_tf32_multi(
    const float4* __restrict__ x,  float4* __restrict__ xr,
    const float4* __restrict__ wq, const float4* __restrict__ wk,
    const float4* __restrict__ wv, const float4* __restrict__ wo,
    float4* __restrict__ wr, int xn4, int wn4)
{
    const int y = blockIdx.y;
    const int i = blockIdx.x * blockDim.x + threadIdx.x;
    const float4* in;
    float4* out;
    int n4;
    if (y == 0)      { in = x;  out = xr;           n4 = xn4; }
    else if (y == 1) { in = wq; out = wr;           n4 = wn4; }
    else if (y == 2) { in = wk; out = wr + wn4;     n4 = wn4; }
    else if (y == 3) { in = wv; out = wr + 2 * wn4; n4 = wn4; }
    else             { in = wo; out = wr + 3 * wn4; n4 = wn4; }
    if (i < n4) {
        float4 v = in[i];
        float4 o;
        o.x = __uint_as_float(f2tf32(v.x));
        o.y = __uint_as_float(f2tf32(v.y));
        o.z = __uint_as_float(f2tf32(v.z));
        o.w = __uint_as_float(f2tf32(v.w));
        out[i] = o;
    }
}

// ---------------------------------------------------------------------------
// tf32 GEMM, cp.async double-buffer (unchanged from round 8)
// ---------------------------------------------------------------------------
__global__ __launch_bounds__(256, 2) void gemm_tf32_cp(
    const float* __restrict__ A, const float* __restrict__ Wbase,
    size_t wstride,
    const float* __restrict__ b0, const float* __restrict__ b1,
    const float* __restrict__ b2,
    float* __restrict__ C0, float* __restrict__ C1, float* __restrict__ C2,
    int M, int N, int K)
{
    __shared__ uint32_t As[2][128 * 32];
    __shared__ uint32_t Bs[2][128 * 32];

    const int z = blockIdx.z;
    const float* W    = Wbase + (size_t)z * wstride;
    const float* bias = (z == 0) ? b0 : (z == 1) ? b1 : b2;
    float*       C    = (z == 0) ? C0 : (z == 1) ? C1 : C2;

    const int tid    = threadIdx.x;
    const int warpId = tid >> 5;
    const int lane   = tid & 31;
    const int r      = lane >> 2;
    const int c      = lane & 3;
    const int warpM  = (warpId >> 2) * 64;
    const int warpN  = (warpId & 3) * 32;
    const int m0     = blockIdx.y * 128;
    const int n0     = blockIdx.x * 128;

    const int gRow = tid >> 1;
    const int gK   = (tid & 1) * 16;
    const float* Ag = A + (size_t)(m0 + gRow) * K + gK;
    const float* Wg = W + (size_t)(n0 + gRow) * K + gK;
    const int swr   = (gRow & 7) << 2;

    uint32_t soffb[4];
#pragma unroll
    for (int j = 0; j < 4; ++j)
        soffb[j] = (uint32_t)(gRow * 32 + ((gK + 4 * j) ^ swr)) * 4;

    const uint32_t asb[2] = { smem_u32(As[0]), smem_u32(As[1]) };
    const uint32_t bsb[2] = { smem_u32(Bs[0]), smem_u32(Bs[1]) };

    const int lrow8 = lane & 7;
    const int tsel  = lane >> 3;
    const int aRow  = warpM + ((tsel & 1) << 3) + lrow8;
    const int aCa   = tsel >> 1;
    const int bRow  = warpN + ((tsel >> 1) << 3) + lrow8;
    const int bCa   = tsel & 1;

    float acc[4][4][4];
#pragma unroll
    for (int mt = 0; mt < 4; ++mt)
#pragma unroll
        for (int nt = 0; nt < 4; ++nt)
#pragma unroll
            for (int q = 0; q < 4; ++q) acc[mt][nt][q] = 0.f;

#pragma unroll
    for (int j = 0; j < 4; ++j) {
        CP_ASYNC16(asb[0] + soffb[j], Ag + 4 * j);
        CP_ASYNC16(bsb[0] + soffb[j], Wg + 4 * j);
    }
    CP_COMMIT();

    int st = 0;
    for (int k0 = 0; k0 < K; k0 += 32) {
        if (k0 + 32 < K) {
            const float* An = Ag + k0 + 32;
            const float* Wn = Wg + k0 + 32;
#pragma unroll
            for (int j = 0; j < 4; ++j) {
                CP_ASYNC16(asb[st ^ 1] + soffb[j], An + 4 * j);
                CP_ASYNC16(bsb[st ^ 1] + soffb[j], Wn + 4 * j);
            }
        }
        CP_COMMIT();
        CP_WAIT1();
        __syncthreads();

        const uint32_t a_s = asb[st], b_s = bsb[st];
#pragma unroll
        for (int ks = 0; ks < 4; ++ks) {
            uint32_t af[4][4];
            const uint32_t aChunk = (uint32_t)((2 * ks + aCa) ^ lrow8) << 4;
#pragma unroll
            for (int mt = 0; mt < 4; ++mt)
                ldsm_x4(a_s + ((uint32_t)(aRow + 16 * mt) << 7) + aChunk, af[mt]);

            uint32_t bf[2][4];
            const uint32_t bChunk = (uint32_t)((2 * ks + bCa) ^ lrow8) << 4;
#pragma unroll
            for (int p = 0; p < 2; ++p)
                ldsm_x4(b_s + ((uint32_t)(bRow + 16 * p) << 7) + bChunk, bf[p]);

#pragma unroll
            for (int nt = 0; nt < 4; ++nt) {
                const uint32_t bb0 = bf[nt >> 1][(nt & 1) << 1];
                const uint32_t bb1 = bf[nt >> 1][((nt & 1) << 1) + 1];
#pragma unroll
                for (int mt = 0; mt < 4; ++mt)
                    mma_tf32(acc[mt][nt], af[mt], bb0, bb1);
            }
        }
        __syncthreads();
        st ^= 1;
    }

#pragma unroll
    for (int nt = 0; nt < 4; ++nt) {
        const int col = n0 + warpN + 8 * nt + 2 * c;
        const float2 bv = *(const float2*)&bias[col];
#pragma unroll
        for (int mt = 0; mt < 4; ++mt) {
            const int row = m0 + warpM + 16 * mt + r;
            float2 o0 = make_float2(acc[mt][nt][0] + bv.x, acc[mt][nt][1] + bv.y);
            float2 o1 = make_float2(acc[mt][nt][2] + bv.x, acc[mt][nt][3] + bv.y);
            *(float2*)&C[(size_t)row * N + col]       = o0;
            *(float2*)&C[(size_t)(row + 8) * N + col] = o1;
        }
    }
}

// ---------------------------------------------------------------------------
// Flash attention, bf16x2, register-prefetched K/V, registerized softmax.
// 4 barriers per key-tile; no serialized tid<64 sections.
// ---------------------------------------------------------------------------
#define ATTN_SMEM_BYTES (6 * 64 * 128)   // 48 KB

__global__ __launch_bounds__(256, 2) void attn_alibi_bf16(
    const float* __restrict__ Q, const float* __restrict__ K,
    const float* __restrict__ V, const unsigned char* __restrict__ pad,
    float* __restrict__ O)
{
    const int qt = blockIdx.x;
    const int bh = blockIdx.y;
    const int b  = bh >> 4;
    const int h  = bh & 15;

    extern __shared__ char smc[];
    char* Qh = smc;
    char* Ql = Qh + 8192;
    char* Kh = Ql + 8192;    // also P hi
    char* Kl = Kh + 8192;    // also P lo
    char* Vh = Kl + 8192;
    char* Vl = Vh + 8192;

    __shared__ float redA[64][2];   // max exchange
    __shared__ float redB[64][2];   // sum exchange
    __shared__ float pads[64];

    const int tid  = threadIdx.x;
    const int warp = tid >> 5;
    const int lane = tid & 31;
    const int r    = lane >> 2;
    const int c    = lane & 3;
    const int wq   = warp >> 1;
    const int wk   = warp & 1;

    const int lrow8 = lane & 7;
    const int tsel  = lane >> 3;

    const int aRow = 16 * wq + ((tsel & 1) << 3) + lrow8;
    const int aCa  = tsel >> 1;
    const int aR7  = aRow & 7;
    const uint32_t qh_b = smem_u32(Qh) + (uint32_t)aRow * 128;
    const uint32_t ql_b = smem_u32(Ql) + (uint32_t)aRow * 128;
    const uint32_t ph_b = smem_u32(Kh) + (uint32_t)aRow * 128;
    const uint32_t pl_b = smem_u32(Kl) + (uint32_t)aRow * 128;

    const int kRow = 32 * wk + ((tsel >> 1) << 3) + lrow8;
    const int kCa  = tsel & 1;
    const int kR7  = kRow & 7;
    const uint32_t kh_b = smem_u32(Kh) + (uint32_t)kRow * 128;
    const uint32_t kl_b = smem_u32(Kl) + (uint32_t)kRow * 128;

    const int vRow = ((tsel & 1) << 3) + lrow8;
    const int vCa  = 4 * wk + (tsel >> 1);
    const int vR7  = vRow & 7;
    const uint32_t vh_b = smem_u32(Vh) + (uint32_t)vRow * 128;
    const uint32_t vl_b = smem_u32(Vl) + (uint32_t)vRow * 128;

    const float slope = exp2f(-0.5f * (float)(h + 1));

    const float* Qb = Q + ((size_t)b * SEQ_L) * D_MODEL + h * HEAD_DIM;
    const float* Kb = K + ((size_t)b * SEQ_L) * D_MODEL + h * HEAD_DIM;
    const float* Vb = V + ((size_t)b * SEQ_L) * D_MODEL + h * HEAD_DIM;
    const unsigned char* padb = pad + (size_t)b * SEQ_L;

    const int ldRow = tid >> 2;
    const int ldC0  = (tid & 3) * 2;
    const uint32_t off0 = (uint32_t)ldRow * 128 +
                          ((uint32_t)(ldC0 ^ (ldRow & 7)) << 4);
    const uint32_t off1 = (uint32_t)ldRow * 128 +
                          ((uint32_t)((ldC0 + 1) ^ (ldRow & 7)) << 4);
    const int ldD0 = (tid & 3) * 16;

    // ---- load Q tile (scaled by 0.125) ----
    {
        const float* src = Qb + (size_t)(qt * 64 + ldRow) * D_MODEL + ldD0;
        uint32_t hw[8], lw[8];
#pragma unroll
        for (int j = 0; j < 4; ++j) {
            float4 v = *(const float4*)(src + 4 * j);
            split_pair(v.x * 0.125f, v.y * 0.125f, hw[2 * j], lw[2 * j]);
            split_pair(v.z * 0.125f, v.w * 0.125f, hw[2 * j + 1], lw[2 * j + 1]);
        }
        *(uint4*)(Qh + off0) = make_uint4(hw[0], hw[1], hw[2], hw[3]);
        *(uint4*)(Qh + off1) = make_uint4(hw[4], hw[5], hw[6], hw[7]);
        *(uint4*)(Ql + off0) = make_uint4(lw[0], lw[1], lw[2], lw[3]);
        *(uint4*)(Ql + off1) = make_uint4(lw[4], lw[5], lw[6], lw[7]);
    }

    float Oacc[4][4];
#pragma unroll
    for (int nt = 0; nt < 4; ++nt)
#pragma unroll
        for (int q = 0; q < 4; ++q) Oacc[nt][q] = 0.f;

    const int row0 = 16 * wq + r;
    const int kt_lo = (qt >= 8) ? (qt - 8) : 0;

    // registerized softmax state (replicated across the 8 lanes sharing a row)
    float m0r = -1e30f, m1r = -1e30f, l0r = 0.f, l1r = 0.f;

    // ---- prefetch first K/V tile into registers ----
    float4 pk[4], pv[4];
    float padreg = 0.f;
    {
        const float* ksrc = Kb + (size_t)(kt_lo * 64 + ldRow) * D_MODEL + ldD0;
        const float* vsrc = Vb + (size_t)(kt_lo * 64 + ldRow) * D_MODEL + ldD0;
#pragma unroll
        for (int j = 0; j < 4; ++j) {
            pk[j] = *(const float4*)(ksrc + 4 * j);
            pv[j] = *(const float4*)(vsrc + 4 * j);
        }
        if (tid < 64) padreg = padb[kt_lo * 64 + tid] ? -1e30f : 0.f;
    }

    for (int kt = kt_lo; kt <= qt; ++kt) {
        __syncthreads();   // previous tile's smem reads (P/V/K) complete
        // ---- store prefetched K/V ----
        {
            uint32_t hw[8], lw[8];
#pragma unroll
            for (int j = 0; j < 4; ++j) {
                split_pair(pk[j].x, pk[j].y, hw[2 * j], lw[2 * j]);
                split_pair(pk[j].z, pk[j].w, hw[2 * j + 1], lw[2 * j + 1]);
            }
            *(uint4*)(Kh + off0) = make_uint4(hw[0], hw[1], hw[2], hw[3]);
            *(uint4*)(Kh + off1) = make_uint4(hw[4], hw[5], hw[6], hw[7]);
            *(uint4*)(Kl + off0) = make_uint4(lw[0], lw[1], lw[2], lw[3]);
            *(uint4*)(Kl + off1) = make_uint4(lw[4], lw[5], lw[6], lw[7]);
#pragma unroll
            for (int j = 0; j < 4; ++j) {
                split_pair(pv[j].x, pv[j].y, hw[2 * j], lw[2 * j]);
                split_pair(pv[j].z, pv[j].w, hw[2 * j + 1], lw[2 * j + 1]);
            }
            *(uint4*)(Vh + off0) = make_uint4(hw[0], hw[1], hw[2], hw[3]);
            *(uint4*)(Vh + off1) = make_uint4(hw[4], hw[5], hw[6], hw[7]);
            *(uint4*)(Vl + off0) = make_uint4(lw[0], lw[1], lw[2], lw[3]);
            *(uint4*)(Vl + off1) = make_uint4(lw[4], lw[5], lw[6], lw[7]);
        }
        if (tid < 64) pads[tid] = padreg;
        __syncthreads();

        // ---- prefetch next tile (overlaps with compute below) ----
        if (kt < qt) {
            const float* ksrc = Kb + (size_t)((kt + 1) * 64 + ldRow) * D_MODEL + ldD0;
            const float* vsrc = Vb + (size_t)((kt + 1) * 64 + ldRow) * D_MODEL + ldD0;
#pragma unroll
            for (int j = 0; j < 4; ++j) {
                pk[j] = *(const float4*)(ksrc + 4 * j);
                pv[j] = *(const float4*)(vsrc + 4 * j);
            }
            if (tid < 64) padreg = padb[(kt + 1) * 64 + tid] ? -1e30f : 0.f;
        }

        // ---- S = Q.K^T ----
        float Sacc[4][4];
#pragma unroll
        for (int nt = 0; nt < 4; ++nt)
#pragma unroll
            for (int q = 0; q < 4; ++q) Sacc[nt][q] = 0.f;

#pragma unroll
        for (int ks = 0; ks < 4; ++ks) {
            uint32_t ah[4], al[4];
            const uint32_t axo = ((uint32_t)((2 * ks + aCa) ^ aR7) << 4);
            ldsm_x4(qh_b + axo, ah);
            ldsm_x4(ql_b + axo, al);
            uint32_t bhf[2][4], blf[2][4];
            const uint32_t kxo = ((uint32_t)((2 * ks + kCa) ^ kR7) << 4);
#pragma unroll
            for (int p = 0; p < 2; ++p) {
                ldsm_x4(kh_b + (uint32_t)p * 2048 + kxo, bhf[p]);
                ldsm_x4(kl_b + (uint32_t)p * 2048 + kxo, blf[p]);
            }
#pragma unroll
            for (int nt = 0; nt < 4; ++nt) {
                const uint32_t bh0 = bhf[nt >> 1][(nt & 1) << 1];
                const uint32_t bh1 = bhf[nt >> 1][((nt & 1) << 1) + 1];
                const uint32_t bl0 = blf[nt >> 1][(nt & 1) << 1];
                const uint32_t bl1 = blf[nt >> 1][((nt & 1) << 1) + 1];
                mma_bf16(Sacc[nt], ah, bh0, bh1);
                mma_bf16(Sacc[nt], ah, bl0, bl1);
                mma_bf16(Sacc[nt], al, bh0, bh1);
            }
        }

        // ---- mask + ALiBi + partial row max ----
        const int gi0 = qt * 64 + row0;
        const int gi1 = gi0 + 8;
        float mx0 = -1e30f, mx1 = -1e30f;
#pragma unroll
        for (int nt = 0; nt < 4; ++nt) {
            const int jl = 32 * wk + 8 * nt + 2 * c;
            const int gj0 = kt * 64 + jl, gj1 = gj0 + 1;
            const float pd0 = pads[jl], pd1 = pads[jl + 1];
            float s;
            s = Sacc[nt][0] + slope * (float)(gj0 - gi0) + pd0;
            if (gj0 > gi0 || gj0 < gi0 - WINDOW) s = -1e30f;
            Sacc[nt][0] = s; mx0 = fmaxf(mx0, s);
            s = Sacc[nt][1] + slope * (float)(gj1 - gi0) + pd1;
            if (gj1 > gi0 || gj1 < gi0 - WINDOW) s = -1e30f;
            Sacc[nt][1] = s; mx0 = fmaxf(mx0, s);
            s = Sacc[nt][2] + slope * (float)(gj0 - gi1) + pd0;
            if (gj0 > gi1 || gj0 < gi1 - WINDOW) s = -1e30f;
            Sacc[nt][2] = s; mx1 = fmaxf(mx1, s);
            s = Sacc[nt][3] + slope * (float)(gj1 - gi1) + pd1;
            if (gj1 > gi1 || gj1 < gi1 - WINDOW) s = -1e30f;
            Sacc[nt][3] = s; mx1 = fmaxf(mx1, s);
        }
        mx0 = fmaxf(mx0, __shfl_xor_sync(0xffffffffu, mx0, 1));
        mx0 = fmaxf(mx0, __shfl_xor_sync(0xffffffffu, mx0, 2));
        mx1 = fmaxf(mx1, __shfl_xor_sync(0xffffffffu, mx1, 1));
        mx1 = fmaxf(mx1, __shfl_xor_sync(0xffffffffu, mx1, 2));
        if (c == 0) { redA[row0][wk] = mx0; redA[row0 + 8][wk] = mx1; }
        __syncthreads();   // max exchange; also fences K reads before P writes

        // ---- registerized m/l update (replicated per row owners) ----
        const float mt0 = fmaxf(redA[row0][0], redA[row0][1]);
        const float mt1 = fmaxf(redA[row0 + 8][0], redA[row0 + 8][1]);
        const float mn0 = fmaxf(m0r, mt0);
        const float mn1 = fmaxf(m1r, mt1);
        const float sc0 = __expf(m0r - mn0);
        const float sc1 = __expf(m1r - mn1);
        m0r = mn0; m1r = mn1;
        l0r *= sc0; l1r *= sc1;

        // ---- P = exp(S-m); write bf16x2 P; rescale O ----
        float rs0 = 0.f, rs1 = 0.f;
        const uint32_t prow0 = (uint32_t)row0 * 128;
        const uint32_t prow1 = (uint32_t)(row0 + 8) * 128;
        const uint32_t pxr = (uint32_t)(row0 & 7);
#pragma unroll
        for (int nt = 0; nt < 4; ++nt) {
            float p0 = (Sacc[nt][0] < -1e29f) ? 0.f : __expf(Sacc[nt][0] - mn0);
            float p1 = (Sacc[nt][1] < -1e29f) ? 0.f : __expf(Sacc[nt][1] - mn0);
            float p2 = (Sacc[nt][2] < -1e29f) ? 0.f : __expf(Sacc[nt][2] - mn1);
            float p3 = (Sacc[nt][3] < -1e29f) ? 0.f : __expf(Sacc[nt][3] - mn1);
            rs0 += p0 + p1; rs1 += p2 + p3;
            const uint32_t cxo = (((uint32_t)(4 * wk + nt) ^ pxr) << 4) + 4 * c;
            uint32_t ph, pl;
            split_pair(p0, p1, ph, pl);
            *(uint32_t*)(Kh + prow0 + cxo) = ph;
            *(uint32_t*)(Kl + prow0 + cxo) = pl;
            split_pair(p2, p3, ph, pl);
            *(uint32_t*)(Kh + prow1 + cxo) = ph;
            *(uint32_t*)(Kl + prow1 + cxo) = pl;
            Oacc[nt][0] *= sc0; Oacc[nt][1] *= sc0;
            Oacc[nt][2] *= sc1; Oacc[nt][3] *= sc1;
        }
        rs0 += __shfl_xor_sync(0xffffffffu, rs0, 1);
        rs0 += __shfl_xor_sync(0xffffffffu, rs0, 2);
        rs1 += __shfl_xor_sync(0xffffffffu, rs1, 1);
        rs1 += __shfl_xor_sync(0xffffffffu, rs1, 2);
        if (c == 0) { redB[row0][wk] = rs0; redB[row0 + 8][wk] = rs1; }
        __syncthreads();   // P visible + sum exchange

        l0r += redB[row0][0] + redB[row0][1];
        l1r += redB[row0 + 8][0] + redB[row0 + 8][1];

        // ---- O += P.V ----
#pragma unroll
        for (int ks = 0; ks < 4; ++ks) {
            uint32_t ah[4], al[4];
            const uint32_t axo = ((uint32_t)((2 * ks + aCa) ^ aR7) << 4);
            ldsm_x4(ph_b + axo, ah);
            ldsm_x4(pl_b + axo, al);
            uint32_t bvh[2][4], bvl[2][4];
#pragma unroll
            for (int p = 0; p < 2; ++p) {
                const uint32_t vxo = (uint32_t)ks * 2048 +
                    (((uint32_t)(vCa + 2 * p) ^ vR7) << 4);
                ldsm_x4_t(vh_b + vxo, bvh[p]);
                ldsm_x4_t(vl_b + vxo, bvl[p]);
            }
#pragma unroll
            for (int nt = 0; nt < 4; ++nt) {
                const uint32_t bh0 = bvh[nt >> 1][(nt & 1) << 1];
                const uint32_t bh1 = bvh[nt >> 1][((nt & 1) << 1) + 1];
                const uint32_t bl0 = bvl[nt >> 1][(nt & 1) << 1];
                const uint32_t bl1 = bvl[nt >> 1][((nt & 1) << 1) + 1];
                mma_bf16(Oacc[nt], ah, bh0, bh1);
                mma_bf16(Oacc[nt], ah, bl0, bl1);
                mma_bf16(Oacc[nt], al, bh0, bh1);
            }
        }
    }

    const float inv0 = 1.f / l0r;
    const float inv1 = 1.f / l1r;
    const int gi0 = qt * 64 + row0;
    float* Ob = O + ((size_t)b * SEQ_L + gi0) * D_MODEL + h * HEAD_DIM;
#pragma unroll
    for (int nt = 0; nt < 4; ++nt) {
        const int dcol = 32 * wk + 8 * nt + 2 * c;
        *(float2*)(Ob + dcol) = make_float2(
            __uint_as_float(f2tf32(Oacc[nt][0] * inv0)),
            __uint_as_float(f2tf32(Oacc[nt][1] * inv0)));
        *(float2*)(Ob + 8 * D_MODEL + dcol) = make_float2(
            __uint_as_float(f2tf32(Oacc[nt][2] * inv1)),
            __uint_as_float(f2tf32(Oacc[nt][3] * inv1)));
    }
}

// ---------------------------------------------------------------------------
extern "C" void kernel_launch(void* const* d_in, const int* in_sizes, int n_in,
                              void* d_out, int out_size)
{
    const float* x  = (const float*)d_in[0];
    const unsigned char* pad = (const unsigned char*)d_in[1];
    const float* Wq = (const float*)d_in[2];
    const float* bq = (const float*)d_in[3];
    const float* Wk = (const float*)d_in[4];
    const float* bk = (const float*)d_in[5];
    const float* Wv = (const float*)d_in[6];
    const float* bv = (const float*)d_in[7];
    const float* Wo = (const float*)d_in[8];
    const float* bo = (const float*)d_in[9];
    float* out = (float*)d_out;

    float *q, *k, *v, *att, *xr, *wr;
    cudaGetSymbolAddress((void**)&q,   g_q);
    cudaGetSymbolAddress((void**)&k,   g_k);
    cudaGetSymbolAddress((void**)&v,   g_v);
    cudaGetSymbolAddress((void**)&att, g_att);
    cudaGetSymbolAddress((void**)&xr,  g_xr);
    cudaGetSymbolAddress((void**)&wr,  g_wr);

    cudaFuncSetAttribute(attn_alibi_bf16,
                         cudaFuncAttributeMaxDynamicSharedMemorySize,
                         ATTN_SMEM_BYTES);

    const int WN  = D_MODEL * D_MODEL;         // 1M elts per weight
    const int xn4 = MTOT * D_MODEL / 4;        // 2M float4
    const int wn4 = WN / 4;                    // 256K float4
    dim3 rgrid((xn4 + 255) / 256, 5);
    round_tf32_multi<<<rgrid, 256>>>((const float4*)x, (float4*)xr,
                                     (const float4*)Wq, (const float4*)Wk,
                                     (const float4*)Wv, (const float4*)Wo,
                                     (float4*)wr, xn4, wn4);

    dim3 qkv_grid(D_MODEL / 128, MTOT / 128, 3); // (8, 64, 3)
    gemm_tf32_cp<<<qkv_grid, 256>>>(xr, wr, (size_t)WN, bq, bk, bv,
                                    q, k, v, MTOT, D_MODEL, D_MODEL);

    dim3 agrid(SEQ_L / 64, BATCH * N_HEADS);   // (32, 64)
    attn_alibi_bf16<<<agrid, 256, ATTN_SMEM_BYTES>>>(q, k, v, pad, att);

    dim3 o_grid(D_MODEL / 128, MTOT / 128, 1);
    gemm_tf32_cp<<<o_grid, 256>>>(att, wr + 3 * WN, (size_t)0, bo, bo, bo,
                                  out, out, out, MTOT, D_MODEL, D_MODEL);
}

// round 10
// speedup vs baseline: 1.0614x; 1.0614x over previous
#include <cuda_runtime.h>
#include <cuda_bf16.h>
#include <cstdint>

#define D_MODEL  1024
#define N_HEADS  16
#define HEAD_DIM 64
#define SEQ_L    2048
#define BATCH    4
#define WINDOW   512

#define MTOT (BATCH * SEQ_L)          // 8192

__device__ float g_q[MTOT * D_MODEL];
__device__ float g_k[MTOT * D_MODEL];
__device__ float g_v[MTOT * D_MODEL];
__device__ float g_att[MTOT * D_MODEL];
__device__ float g_xr[MTOT * D_MODEL];          // pre-rounded x
__device__ float g_wr[4 * D_MODEL * D_MODEL];   // pre-rounded Wq,Wk,Wv,Wo

__device__ __forceinline__ uint32_t f2tf32(float f) {
    uint32_t u;
    asm("cvt.rna.tf32.f32 %0, %1;" : "=r"(u) : "f"(f));
    return u;
}
__device__ __forceinline__ void mma_tf32(float* d, const uint32_t* a,
                                         uint32_t b0, uint32_t b1) {
    asm volatile(
        "mma.sync.aligned.m16n8k8.row.col.f32.tf32.tf32.f32 "
        "{%0,%1,%2,%3}, {%4,%5,%6,%7}, {%8,%9}, {%0,%1,%2,%3};"
        : "+f"(d[0]), "+f"(d[1]), "+f"(d[2]), "+f"(d[3])
        : "r"(a[0]), "r"(a[1]), "r"(a[2]), "r"(a[3]), "r"(b0), "r"(b1));
}
__device__ __forceinline__ void mma_bf16(float* d, const uint32_t* a,
                                         uint32_t b0, uint32_t b1) {
    asm volatile(
        "mma.sync.aligned.m16n8k16.row.col.f32.bf16.bf16.f32 "
        "{%0,%1,%2,%3}, {%4,%5,%6,%7}, {%8,%9}, {%0,%1,%2,%3};"
        : "+f"(d[0]), "+f"(d[1]), "+f"(d[2]), "+f"(d[3])
        : "r"(a[0]), "r"(a[1]), "r"(a[2]), "r"(a[3]), "r"(b0), "r"(b1));
}
__device__ __forceinline__ uint32_t smem_u32(const void* p) {
    uint32_t a;
    asm("{ .reg .u64 t; cvta.to.shared.u64 t, %1; cvt.u32.u64 %0, t; }"
        : "=r"(a) : "l"(p));
    return a;
}
__device__ __forceinline__ void ldsm_x4(uint32_t addr, uint32_t* r) {
    asm volatile(
        "ldmatrix.sync.aligned.m8n8.x4.shared.b16 {%0,%1,%2,%3}, [%4];"
        : "=r"(r[0]), "=r"(r[1]), "=r"(r[2]), "=r"(r[3]) : "r"(addr));
}
__device__ __forceinline__ void ldsm_x4_t(uint32_t addr, uint32_t* r) {
    asm volatile(
        "ldmatrix.sync.aligned.m8n8.x4.trans.shared.b16 {%0,%1,%2,%3}, [%4];"
        : "=r"(r[0]), "=r"(r[1]), "=r"(r[2]), "=r"(r[3]) : "r"(addr));
}
__device__ __forceinline__ void split_pair(float e0, float e1,
                                           uint32_t& h, uint32_t& l) {
    __nv_bfloat16 b0 = __float2bfloat16_rn(e0), b1 = __float2bfloat16_rn(e1);
    h = ((uint32_t)__bfloat16_as_ushort(b1) << 16) | __bfloat16_as_ushort(b0);
    float r0 = e0 - __bfloat162float(b0), r1 = e1 - __bfloat162float(b1);
    __nv_bfloat16 c0 = __float2bfloat16_rn(r0), c1 = __float2bfloat16_rn(r1);
    l = ((uint32_t)__bfloat16_as_ushort(c1) << 16) | __bfloat16_as_ushort(c0);
}

#define CP_ASYNC16(dst, src) \
    asm volatile("cp.async.cg.shared.global [%0], [%1], 16;" \
                 :: "r"(dst), "l"(src))
#define CP_COMMIT() asm volatile("cp.async.commit_group;")
#define CP_WAITG1() asm volatile("cp.async.wait_group 1;" ::: "memory")

// ---------------------------------------------------------------------------
// Merged pre-round pass: y=0 -> x (xn4), y=1..4 -> Wq/Wk/Wv/Wo (wn4 each).
// ---------------------------------------------------------------------------
__global__ void round_tf32_multi(
    const float4* __restrict__ x,  float4* __restrict__ xr,
    const float4* __restrict__ wq, const float4* __restrict__ wk,
    const float4* __restrict__ wv, const float4* __restrict__ wo,
    float4* __restrict__ wr, int xn4, int wn4)
{
    const int y = blockIdx.y;
    const int i = blockIdx.x * blockDim.x + threadIdx.x;
    const float4* in;
    float4* out;
    int n4;
    if (y == 0)      { in = x;  out = xr;           n4 = xn4; }
    else if (y == 1) { in = wq; out = wr;           n4 = wn4; }
    else if (y == 2) { in = wk; out = wr + wn4;     n4 = wn4; }
    else if (y == 3) { in = wv; out = wr + 2 * wn4; n4 = wn4; }
    else             { in = wo; out = wr + 3 * wn4; n4 = wn4; }
    if (i < n4) {
        float4 v = in[i];
        float4 o;
        o.x = __uint_as_float(f2tf32(v.x));
        o.y = __uint_as_float(f2tf32(v.y));
        o.z = __uint_as_float(f2tf32(v.z));
        o.w = __uint_as_float(f2tf32(v.w));
        out[i] = o;
    }
}

// ---------------------------------------------------------------------------
// tf32 GEMM, 3-stage cp.async pipeline, ONE barrier per 32-K iteration.
// C[m][n] = sum_k A[m][k]*W[n][k] + bias[n].  blockIdx.z selects (W,b,C).
// Dynamic smem: As 3x4096 words, Bs 3x4096 words = 96 KB.
// ---------------------------------------------------------------------------
#define G_STAGE_W 4096                       // words per stage (128 rows x 32)
#define G_SMEM_BYTES (6 * G_STAGE_W * 4)     // 96 KB
#define NIT 32                               // K / 32

__global__ __launch_bounds__(256) void gemm_tf32_cp3(
    const float* __restrict__ A, const float* __restrict__ Wbase,
    size_t wstride,
    const float* __restrict__ b0, const float* __restrict__ b1,
    const float* __restrict__ b2,
    float* __restrict__ C0, float* __restrict__ C1, float* __restrict__ C2,
    int M, int N, int K)
{
    extern __shared__ uint32_t gsm[];
    const int z = blockIdx.z;
    const float* W    = Wbase + (size_t)z * wstride;
    const float* bias = (z == 0) ? b0 : (z == 1) ? b1 : b2;
    float*       C    = (z == 0) ? C0 : (z == 1) ? C1 : C2;

    const int tid    = threadIdx.x;
    const int warpId = tid >> 5;
    const int lane   = tid & 31;
    const int r      = lane >> 2;
    const int c      = lane & 3;
    const int warpM  = (warpId >> 2) * 64;
    const int warpN  = (warpId & 3) * 32;
    const int m0     = blockIdx.y * 128;
    const int n0     = blockIdx.x * 128;

    const int gRow = tid >> 1;
    const int gK   = (tid & 1) * 16;
    const float* Ag = A + (size_t)(m0 + gRow) * K + gK;
    const float* Wg = W + (size_t)(n0 + gRow) * K + gK;
    const int swr   = (gRow & 7) << 2;

    uint32_t soffb[4];
#pragma unroll
    for (int j = 0; j < 4; ++j)
        soffb[j] = (uint32_t)(gRow * 32 + ((gK + 4 * j) ^ swr)) * 4;

    uint32_t asb[3], bsb[3];
#pragma unroll
    for (int s = 0; s < 3; ++s) {
        asb[s] = smem_u32(gsm + s * G_STAGE_W);
        bsb[s] = smem_u32(gsm + (3 + s) * G_STAGE_W);
    }

    const int lrow8 = lane & 7;
    const int tsel  = lane >> 3;
    const int aRow  = warpM + ((tsel & 1) << 3) + lrow8;
    const int aCa   = tsel >> 1;
    const int bRow  = warpN + ((tsel >> 1) << 3) + lrow8;
    const int bCa   = tsel & 1;

    float acc[4][4][4];
#pragma unroll
    for (int mt = 0; mt < 4; ++mt)
#pragma unroll
        for (int nt = 0; nt < 4; ++nt)
#pragma unroll
            for (int q = 0; q < 4; ++q) acc[mt][nt][q] = 0.f;

    // prologue: stages 0,1
#pragma unroll
    for (int s = 0; s < 2; ++s) {
        const float* An = Ag + s * 32;
        const float* Wn = Wg + s * 32;
#pragma unroll
        for (int j = 0; j < 4; ++j) {
            CP_ASYNC16(asb[s] + soffb[j], An + 4 * j);
            CP_ASYNC16(bsb[s] + soffb[j], Wn + 4 * j);
        }
        CP_COMMIT();
    }

    int st = 0;        // stage being computed
    int sl = 2;        // stage being loaded (= (i+2)%3)
    for (int i = 0; i < NIT; ++i) {
        CP_WAITG1();       // stage i arrived (all but newest group done)
        __syncthreads();   // data visible; stage sl fully consumed by all warps

        if (i + 2 < NIT) {
            const float* An = Ag + (i + 2) * 32;
            const float* Wn = Wg + (i + 2) * 32;
#pragma unroll
            for (int j = 0; j < 4; ++j) {
                CP_ASYNC16(asb[sl] + soffb[j], An + 4 * j);
                CP_ASYNC16(bsb[sl] + soffb[j], Wn + 4 * j);
            }
        }
        CP_COMMIT();

        const uint32_t a_s = asb[st], b_s = bsb[st];
#pragma unroll
        for (int ks = 0; ks < 4; ++ks) {
            uint32_t af[4][4];
            const uint32_t aChunk = (uint32_t)((2 * ks + aCa) ^ lrow8) << 4;
#pragma unroll
            for (int mt = 0; mt < 4; ++mt)
                ldsm_x4(a_s + ((uint32_t)(aRow + 16 * mt) << 7) + aChunk, af[mt]);

            uint32_t bf[2][4];
            const uint32_t bChunk = (uint32_t)((2 * ks + bCa) ^ lrow8) << 4;
#pragma unroll
            for (int p = 0; p < 2; ++p)
                ldsm_x4(b_s + ((uint32_t)(bRow + 16 * p) << 7) + bChunk, bf[p]);

#pragma unroll
            for (int nt = 0; nt < 4; ++nt) {
                const uint32_t bb0 = bf[nt >> 1][(nt & 1) << 1];
                const uint32_t bb1 = bf[nt >> 1][((nt & 1) << 1) + 1];
#pragma unroll
                for (int mt = 0; mt < 4; ++mt)
                    mma_tf32(acc[mt][nt], af[mt], bb0, bb1);
            }
        }
        st = (st == 2) ? 0 : st + 1;
        sl = (sl == 2) ? 0 : sl + 1;
    }

#pragma unroll
    for (int nt = 0; nt < 4; ++nt) {
        const int col = n0 + warpN + 8 * nt + 2 * c;
        const float2 bv = *(const float2*)&bias[col];
#pragma unroll
        for (int mt = 0; mt < 4; ++mt) {
            const int row = m0 + warpM + 16 * mt + r;
            float2 o0 = make_float2(acc[mt][nt][0] + bv.x, acc[mt][nt][1] + bv.y);
            float2 o1 = make_float2(acc[mt][nt][2] + bv.x, acc[mt][nt][3] + bv.y);
            *(float2*)&C[(size_t)row * N + col]       = o0;
            *(float2*)&C[(size_t)(row + 8) * N + col] = o1;
        }
    }
}

// ---------------------------------------------------------------------------
// Flash attention, bf16x2 (3-term split), m16n8k16 mma — round-8 version.
// ---------------------------------------------------------------------------
#define ATTN_SMEM_BYTES (6 * 64 * 128)   // 48 KB

__global__ __launch_bounds__(256) void attn_alibi_bf16(
    const float* __restrict__ Q, const float* __restrict__ K,
    const float* __restrict__ V, const unsigned char* __restrict__ pad,
    float* __restrict__ O)
{
    const int qt = blockIdx.x;
    const int bh = blockIdx.y;
    const int b  = bh >> 4;
    const int h  = bh & 15;

    extern __shared__ char smc[];
    char* Qh = smc;
    char* Ql = Qh + 8192;
    char* Kh = Ql + 8192;    // also P hi
    char* Kl = Kh + 8192;    // also P lo
    char* Vh = Kl + 8192;
    char* Vl = Vh + 8192;

    __shared__ float red[64][2];
    __shared__ float m_s[64], l_s[64], sc_s[64], pads[64];

    const int tid  = threadIdx.x;
    const int warp = tid >> 5;
    const int lane = tid & 31;
    const int r    = lane >> 2;
    const int c    = lane & 3;
    const int wq   = warp >> 1;
    const int wk   = warp & 1;

    const int lrow8 = lane & 7;
    const int tsel  = lane >> 3;

    const int aRow = 16 * wq + ((tsel & 1) << 3) + lrow8;
    const int aCa  = tsel >> 1;
    const int aR7  = aRow & 7;
    const uint32_t qh_b = smem_u32(Qh) + (uint32_t)aRow * 128;
    const uint32_t ql_b = smem_u32(Ql) + (uint32_t)aRow * 128;
    const uint32_t ph_b = smem_u32(Kh) + (uint32_t)aRow * 128;
    const uint32_t pl_b = smem_u32(Kl) + (uint32_t)aRow * 128;

    const int kRow = 32 * wk + ((tsel >> 1) << 3) + lrow8;
    const int kCa  = tsel & 1;
    const int kR7  = kRow & 7;
    const uint32_t kh_b = smem_u32(Kh) + (uint32_t)kRow * 128;
    const uint32_t kl_b = smem_u32(Kl) + (uint32_t)kRow * 128;

    const int vRow = ((tsel & 1) << 3) + lrow8;
    const int vCa  = 4 * wk + (tsel >> 1);
    const int vR7  = vRow & 7;
    const uint32_t vh_b = smem_u32(Vh) + (uint32_t)vRow * 128;
    const uint32_t vl_b = smem_u32(Vl) + (uint32_t)vRow * 128;

    const float slope = exp2f(-0.5f * (float)(h + 1));

    const float* Qb = Q + ((size_t)b * SEQ_L) * D_MODEL + h * HEAD_DIM;
    const float* Kb = K + ((size_t)b * SEQ_L) * D_MODEL + h * HEAD_DIM;
    const float* Vb = V + ((size_t)b * SEQ_L) * D_MODEL + h * HEAD_DIM;
    const unsigned char* padb = pad + (size_t)b * SEQ_L;

    const int ldRow = tid >> 2;
    const int ldC0  = (tid & 3) * 2;
    const uint32_t off0 = (uint32_t)ldRow * 128 +
                          ((uint32_t)(ldC0 ^ (ldRow & 7)) << 4);
    const uint32_t off1 = (uint32_t)ldRow * 128 +
                          ((uint32_t)((ldC0 + 1) ^ (ldRow & 7)) << 4);
    const int ldD0 = (tid & 3) * 16;

    {
        const float* src = Qb + (size_t)(qt * 64 + ldRow) * D_MODEL + ldD0;
        uint32_t hw[8], lw[8];
#pragma unroll
        for (int j = 0; j < 4; ++j) {
            float4 v = *(const float4*)(src + 4 * j);
            split_pair(v.x * 0.125f, v.y * 0.125f, hw[2 * j], lw[2 * j]);
            split_pair(v.z * 0.125f, v.w * 0.125f, hw[2 * j + 1], lw[2 * j + 1]);
        }
        *(uint4*)(Qh + off0) = make_uint4(hw[0], hw[1], hw[2], hw[3]);
        *(uint4*)(Qh + off1) = make_uint4(hw[4], hw[5], hw[6], hw[7]);
        *(uint4*)(Ql + off0) = make_uint4(lw[0], lw[1], lw[2], lw[3]);
        *(uint4*)(Ql + off1) = make_uint4(lw[4], lw[5], lw[6], lw[7]);
    }
    if (tid < 64) { m_s[tid] = -1e30f; l_s[tid] = 0.f; }

    float Oacc[4][4];
#pragma unroll
    for (int nt = 0; nt < 4; ++nt)
#pragma unroll
        for (int q = 0; q < 4; ++q) Oacc[nt][q] = 0.f;

    const int row0 = 16 * wq + r;
    const int kt_lo = (qt >= 8) ? (qt - 8) : 0;

    for (int kt = kt_lo; kt <= qt; ++kt) {
        __syncthreads();
        {
            const float* ksrc = Kb + (size_t)(kt * 64 + ldRow) * D_MODEL + ldD0;
            const float* vsrc = Vb + (size_t)(kt * 64 + ldRow) * D_MODEL + ldD0;
            uint32_t hw[8], lw[8];
#pragma unroll
            for (int j = 0; j < 4; ++j) {
                float4 v = *(const float4*)(ksrc + 4 * j);
                split_pair(v.x, v.y, hw[2 * j], lw[2 * j]);
                split_pair(v.z, v.w, hw[2 * j + 1], lw[2 * j + 1]);
            }
            *(uint4*)(Kh + off0) = make_uint4(hw[0], hw[1], hw[2], hw[3]);
            *(uint4*)(Kh + off1) = make_uint4(hw[4], hw[5], hw[6], hw[7]);
            *(uint4*)(Kl + off0) = make_uint4(lw[0], lw[1], lw[2], lw[3]);
            *(uint4*)(Kl + off1) = make_uint4(lw[4], lw[5], lw[6], lw[7]);
#pragma unroll
            for (int j = 0; j < 4; ++j) {
                float4 v = *(const float4*)(vsrc + 4 * j);
                split_pair(v.x, v.y, hw[2 * j], lw[2 * j]);
                split_pair(v.z, v.w, hw[2 * j + 1], lw[2 * j + 1]);
            }
            *(uint4*)(Vh + off0) = make_uint4(hw[0], hw[1], hw[2], hw[3]);
            *(uint4*)(Vh + off1) = make_uint4(hw[4], hw[5], hw[6], hw[7]);
            *(uint4*)(Vl + off0) = make_uint4(lw[0], lw[1], lw[2], lw[3]);
            *(uint4*)(Vl + off1) = make_uint4(lw[4], lw[5], lw[6], lw[7]);
        }
        if (tid < 64) pads[tid] = padb[kt * 64 + tid] ? -1e30f : 0.f;
        __syncthreads();

        float Sacc[4][4];
#pragma unroll
        for (int nt = 0; nt < 4; ++nt)
#pragma unroll
            for (int q = 0; q < 4; ++q) Sacc[nt][q] = 0.f;

#pragma unroll
        for (int ks = 0; ks < 4; ++ks) {
            uint32_t ah[4], al[4];
            const uint32_t axo = ((uint32_t)((2 * ks + aCa) ^ aR7) << 4);
            ldsm_x4(qh_b + axo, ah);
            ldsm_x4(ql_b + axo, al);
            uint32_t bhf[2][4], blf[2][4];
            const uint32_t kxo = ((uint32_t)((2 * ks + kCa) ^ kR7) << 4);
#pragma unroll
            for (int p = 0; p < 2; ++p) {
                ldsm_x4(kh_b + (uint32_t)p * 2048 + kxo, bhf[p]);
                ldsm_x4(kl_b + (uint32_t)p * 2048 + kxo, blf[p]);
            }
#pragma unroll
            for (int nt = 0; nt < 4; ++nt) {
                const uint32_t bh0 = bhf[nt >> 1][(nt & 1) << 1];
                const uint32_t bh1 = bhf[nt >> 1][((nt & 1) << 1) + 1];
                const uint32_t bl0 = blf[nt >> 1][(nt & 1) << 1];
                const uint32_t bl1 = blf[nt >> 1][((nt & 1) << 1) + 1];
                mma_bf16(Sacc[nt], ah, bh0, bh1);
                mma_bf16(Sacc[nt], ah, bl0, bl1);
                mma_bf16(Sacc[nt], al, bh0, bh1);
            }
        }

        const int gi0 = qt * 64 + row0;
        const int gi1 = gi0 + 8;
        float mx0 = -1e30f, mx1 = -1e30f;
#pragma unroll
        for (int nt = 0; nt < 4; ++nt) {
            const int jl = 32 * wk + 8 * nt + 2 * c;
            const int gj0 = kt * 64 + jl, gj1 = gj0 + 1;
            const float pd0 = pads[jl], pd1 = pads[jl + 1];
            float s;
            s = Sacc[nt][0] + slope * (float)(gj0 - gi0) + pd0;
            if (gj0 > gi0 || gj0 < gi0 - WINDOW) s = -1e30f;
            Sacc[nt][0] = s; mx0 = fmaxf(mx0, s);
            s = Sacc[nt][1] + slope * (float)(gj1 - gi0) + pd1;
            if (gj1 > gi0 || gj1 < gi0 - WINDOW) s = -1e30f;
            Sacc[nt][1] = s; mx0 = fmaxf(mx0, s);
            s = Sacc[nt][2] + slope * (float)(gj0 - gi1) + pd0;
            if (gj0 > gi1 || gj0 < gi1 - WINDOW) s = -1e30f;
            Sacc[nt][2] = s; mx1 = fmaxf(mx1, s);
            s = Sacc[nt][3] + slope * (float)(gj1 - gi1) + pd1;
            if (gj1 > gi1 || gj1 < gi1 - WINDOW) s = -1e30f;
            Sacc[nt][3] = s; mx1 = fmaxf(mx1, s);
        }
        mx0 = fmaxf(mx0, __shfl_xor_sync(0xffffffffu, mx0, 1));
        mx0 = fmaxf(mx0, __shfl_xor_sync(0xffffffffu, mx0, 2));
        mx1 = fmaxf(mx1, __shfl_xor_sync(0xffffffffu, mx1, 1));
        mx1 = fmaxf(mx1, __shfl_xor_sync(0xffffffffu, mx1, 2));
        if (c == 0) { red[row0][wk] = mx0; red[row0 + 8][wk] = mx1; }
        __syncthreads();

        if (tid < 64) {
            const float mt = fmaxf(red[tid][0], red[tid][1]);
            const float mo = m_s[tid];
            const float mn = fmaxf(mo, mt);
            const float sc = __expf(mo - mn);
            m_s[tid] = mn; sc_s[tid] = sc; l_s[tid] *= sc;
        }
        __syncthreads();

        const float mn0 = m_s[row0], mn1 = m_s[row0 + 8];
        const float sc0 = sc_s[row0], sc1 = sc_s[row0 + 8];
        float rs0 = 0.f, rs1 = 0.f;
        const uint32_t prow0 = (uint32_t)row0 * 128;
        const uint32_t prow1 = (uint32_t)(row0 + 8) * 128;
        const uint32_t pxr = (uint32_t)(row0 & 7);
#pragma unroll
        for (int nt = 0; nt < 4; ++nt) {
            float p0 = (Sacc[nt][0] < -1e29f) ? 0.f : __expf(Sacc[nt][0] - mn0);
            float p1 = (Sacc[nt][1] < -1e29f) ? 0.f : __expf(Sacc[nt][1] - mn0);
            float p2 = (Sacc[nt][2] < -1e29f) ? 0.f : __expf(Sacc[nt][2] - mn1);
            float p3 = (Sacc[nt][3] < -1e29f) ? 0.f : __expf(Sacc[nt][3] - mn1);
            rs0 += p0 + p1; rs1 += p2 + p3;
            const uint32_t cxo = (((uint32_t)(4 * wk + nt) ^ pxr) << 4) + 4 * c;
            uint32_t ph, pl;
            split_pair(p0, p1, ph, pl);
            *(uint32_t*)(Kh + prow0 + cxo) = ph;
            *(uint32_t*)(Kl + prow0 + cxo) = pl;
            split_pair(p2, p3, ph, pl);
            *(uint32_t*)(Kh + prow1 + cxo) = ph;
            *(uint32_t*)(Kl + prow1 + cxo) = pl;
            Oacc[nt][0] *= sc0; Oacc[nt][1] *= sc0;
            Oacc[nt][2] *= sc1; Oacc[nt][3] *= sc1;
        }
        rs0 += __shfl_xor_sync(0xffffffffu, rs0, 1);
        rs0 += __shfl_xor_sync(0xffffffffu, rs0, 2);
        rs1 += __shfl_xor_sync(0xffffffffu, rs1, 1);
        rs1 += __shfl_xor_sync(0xffffffffu, rs1, 2);
        if (c == 0) { red[row0][wk] = rs0; red[row0 + 8][wk] = rs1; }
        __syncthreads();

        if (tid < 64) l_s[tid] += red[tid][0] + red[tid][1];

#pragma unroll
        for (int ks = 0; ks < 4; ++ks) {
            uint32_t ah[4], al[4];
            const uint32_t axo = ((uint32_t)((2 * ks + aCa) ^ aR7) << 4);
            ldsm_x4(ph_b + axo, ah);
            ldsm_x4(pl_b + axo, al);
            uint32_t bvh[2][4], bvl[2][4];
#pragma unroll
            for (int p = 0; p < 2; ++p) {
                const uint32_t vxo = (uint32_t)ks * 2048 +
                    (((uint32_t)(vCa + 2 * p) ^ vR7) << 4);
                ldsm_x4_t(vh_b + vxo, bvh[p]);
                ldsm_x4_t(vl_b + vxo, bvl[p]);
            }
#pragma unroll
            for (int nt = 0; nt < 4; ++nt) {
                const uint32_t bh0 = bvh[nt >> 1][(nt & 1) << 1];
                const uint32_t bh1 = bvh[nt >> 1][((nt & 1) << 1) + 1];
                const uint32_t bl0 = bvl[nt >> 1][(nt & 1) << 1];
                const uint32_t bl1 = bvl[nt >> 1][((nt & 1) << 1) + 1];
                mma_bf16(Oacc[nt], ah, bh0, bh1);
                mma_bf16(Oacc[nt], ah, bl0, bl1);
                mma_bf16(Oacc[nt], al, bh0, bh1);
            }
        }
    }
    __syncthreads();

    const float inv0 = 1.f / l_s[row0];
    const float inv1 = 1.f / l_s[row0 + 8];
    const int gi0 = qt * 64 + row0;
    float* Ob = O + ((size_t)b * SEQ_L + gi0) * D_MODEL + h * HEAD_DIM;
#pragma unroll
    for (int nt = 0; nt < 4; ++nt) {
        const int dcol = 32 * wk + 8 * nt + 2 * c;
        *(float2*)(Ob + dcol) = make_float2(
            __uint_as_float(f2tf32(Oacc[nt][0] * inv0)),
            __uint_as_float(f2tf32(Oacc[nt][1] * inv0)));
        *(float2*)(Ob + 8 * D_MODEL + dcol) = make_float2(
            __uint_as_float(f2tf32(Oacc[nt][2] * inv1)),
            __uint_as_float(f2tf32(Oacc[nt][3] * inv1)));
    }
}

// ---------------------------------------------------------------------------
extern "C" void kernel_launch(void* const* d_in, const int* in_sizes, int n_in,
                              void* d_out, int out_size)
{
    const float* x  = (const float*)d_in[0];
    const unsigned char* pad = (const unsigned char*)d_in[1];
    const float* Wq = (const float*)d_in[2];
    const float* bq = (const float*)d_in[3];
    const float* Wk = (const float*)d_in[4];
    const float* bk = (const float*)d_in[5];
    const float* Wv = (const float*)d_in[6];
    const float* bv = (const float*)d_in[7];
    const float* Wo = (const float*)d_in[8];
    const float* bo = (const float*)d_in[9];
    float* out = (float*)d_out;

    float *q, *k, *v, *att, *xr, *wr;
    cudaGetSymbolAddress((void**)&q,   g_q);
    cudaGetSymbolAddress((void**)&k,   g_k);
    cudaGetSymbolAddress((void**)&v,   g_v);
    cudaGetSymbolAddress((void**)&att, g_att);
    cudaGetSymbolAddress((void**)&xr,  g_xr);
    cudaGetSymbolAddress((void**)&wr,  g_wr);

    cudaFuncSetAttribute(gemm_tf32_cp3,
                         cudaFuncAttributeMaxDynamicSharedMemorySize,
                         G_SMEM_BYTES);
    cudaFuncSetAttribute(attn_alibi_bf16,
                         cudaFuncAttributeMaxDynamicSharedMemorySize,
                         ATTN_SMEM_BYTES);

    const int WN  = D_MODEL * D_MODEL;         // 1M elts per weight
    const int xn4 = MTOT * D_MODEL / 4;        // 2M float4
    const int wn4 = WN / 4;                    // 256K float4
    dim3 rgrid((xn4 + 255) / 256, 5);
    round_tf32_multi<<<rgrid, 256>>>((const float4*)x, (float4*)xr,
                                     (const float4*)Wq, (const float4*)Wk,
                                     (const float4*)Wv, (const float4*)Wo,
                                     (float4*)wr, xn4, wn4);

    dim3 qkv_grid(D_MODEL / 128, MTOT / 128, 3); // (8, 64, 3)
    gemm_tf32_cp3<<<qkv_grid, 256, G_SMEM_BYTES>>>(
        xr, wr, (size_t)WN, bq, bk, bv, q, k, v, MTOT, D_MODEL, D_MODEL);

    dim3 agrid(SEQ_L / 64, BATCH * N_HEADS);   // (32, 64)
    attn_alibi_bf16<<<agrid, 256, ATTN_SMEM_BYTES>>>(q, k, v, pad, att);

    dim3 o_grid(D_MODEL / 128, MTOT / 128, 1);
    gemm_tf32_cp3<<<o_grid, 256, G_SMEM_BYTES>>>(
        att, wr + 3 * WN, (size_t)0, bo, bo, bo, out, out, out,
        MTOT, D_MODEL, D_MODEL);
}

// round 11
// speedup vs baseline: 1.5099x; 1.4225x over previous
#include <cuda_runtime.h>
#include <cuda_bf16.h>
#include <cuda_fp16.h>
#include <cstdint>

#define D_MODEL  1024
#define N_HEADS  16
#define HEAD_DIM 64
#define SEQ_L    2048
#define BATCH    4
#define WINDOW   512

#define MTOT (BATCH * SEQ_L)          // 8192

__device__ float  g_q[MTOT * D_MODEL];
__device__ float  g_k[MTOT * D_MODEL];
__device__ float  g_v[MTOT * D_MODEL];
__device__ __half g_att[MTOT * D_MODEL];           // attention out (fp16)
__device__ __half g_xh[MTOT * D_MODEL];            // fp16-rounded x
__device__ __half g_wh[4 * D_MODEL * D_MODEL];     // fp16 Wq,Wk,Wv,Wo

__device__ __forceinline__ void mma_fp16(float* d, const uint32_t* a,
                                         uint32_t b0, uint32_t b1) {
    asm volatile(
        "mma.sync.aligned.m16n8k16.row.col.f32.f16.f16.f32 "
        "{%0,%1,%2,%3}, {%4,%5,%6,%7}, {%8,%9}, {%0,%1,%2,%3};"
        : "+f"(d[0]), "+f"(d[1]), "+f"(d[2]), "+f"(d[3])
        : "r"(a[0]), "r"(a[1]), "r"(a[2]), "r"(a[3]), "r"(b0), "r"(b1));
}
__device__ __forceinline__ void mma_bf16(float* d, const uint32_t* a,
                                         uint32_t b0, uint32_t b1) {
    asm volatile(
        "mma.sync.aligned.m16n8k16.row.col.f32.bf16.bf16.f32 "
        "{%0,%1,%2,%3}, {%4,%5,%6,%7}, {%8,%9}, {%0,%1,%2,%3};"
        : "+f"(d[0]), "+f"(d[1]), "+f"(d[2]), "+f"(d[3])
        : "r"(a[0]), "r"(a[1]), "r"(a[2]), "r"(a[3]), "r"(b0), "r"(b1));
}
__device__ __forceinline__ uint32_t smem_u32(const void* p) {
    uint32_t a;
    asm("{ .reg .u64 t; cvta.to.shared.u64 t, %1; cvt.u32.u64 %0, t; }"
        : "=r"(a) : "l"(p));
    return a;
}
__device__ __forceinline__ void ldsm_x4(uint32_t addr, uint32_t* r) {
    asm volatile(
        "ldmatrix.sync.aligned.m8n8.x4.shared.b16 {%0,%1,%2,%3}, [%4];"
        : "=r"(r[0]), "=r"(r[1]), "=r"(r[2]), "=r"(r[3]) : "r"(addr));
}
__device__ __forceinline__ void ldsm_x4_t(uint32_t addr, uint32_t* r) {
    asm volatile(
        "ldmatrix.sync.aligned.m8n8.x4.trans.shared.b16 {%0,%1,%2,%3}, [%4];"
        : "=r"(r[0]), "=r"(r[1]), "=r"(r[2]), "=r"(r[3]) : "r"(addr));
}
__device__ __forceinline__ void split_pair(float e0, float e1,
                                           uint32_t& h, uint32_t& l) {
    __nv_bfloat16 b0 = __float2bfloat16_rn(e0), b1 = __float2bfloat16_rn(e1);
    h = ((uint32_t)__bfloat16_as_ushort(b1) << 16) | __bfloat16_as_ushort(b0);
    float r0 = e0 - __bfloat162float(b0), r1 = e1 - __bfloat162float(b1);
    __nv_bfloat16 c0 = __float2bfloat16_rn(r0), c1 = __float2bfloat16_rn(r1);
    l = ((uint32_t)__bfloat16_as_ushort(c1) << 16) | __bfloat16_as_ushort(c0);
}

#define CP_ASYNC16(dst, src) \
    asm volatile("cp.async.cg.shared.global [%0], [%1], 16;" \
                 :: "r"(dst), "l"(src))
#define CP_COMMIT() asm volatile("cp.async.commit_group;")
#define CP_WAITG1() asm volatile("cp.async.wait_group 1;" ::: "memory")

// ---------------------------------------------------------------------------
// Merged fp16 pre-round: y=0 -> x (xn4 float4), y=1..4 -> Wq/Wk/Wv/Wo.
// Each thread: 1 float4 -> 4 halves (8B).
// ---------------------------------------------------------------------------
__global__ void round_fp16_multi(
    const float4* __restrict__ x,  __half* __restrict__ xh,
    const float4* __restrict__ wq, const float4* __restrict__ wk,
    const float4* __restrict__ wv, const float4* __restrict__ wo,
    __half* __restrict__ wh, int xn4, int wn4)
{
    const int y = blockIdx.y;
    const int i = blockIdx.x * blockDim.x + threadIdx.x;
    const float4* in;
    __half* out;
    int n4;
    if (y == 0)      { in = x;  out = xh;               n4 = xn4; }
    else if (y == 1) { in = wq; out = wh;               n4 = wn4; }
    else if (y == 2) { in = wk; out = wh + 4 * wn4;     n4 = wn4; }
    else if (y == 3) { in = wv; out = wh + 8 * wn4;     n4 = wn4; }
    else             { in = wo; out = wh + 12 * wn4;    n4 = wn4; }
    if (i < n4) {
        float4 v = in[i];
        __half2 h0 = __floats2half2_rn(v.x, v.y);
        __half2 h1 = __floats2half2_rn(v.z, v.w);
        *(uint2*)(out + 4 * i) =
            make_uint2(*(uint32_t*)&h0, *(uint32_t*)&h1);
    }
}

// ---------------------------------------------------------------------------
// fp16 GEMM, 3-stage cp.async pipeline, BK=64, one barrier per iteration.
// C[m][n] = sum_k A[m][k]*W[n][k] + bias[n]  (A,W fp16; C fp32).
// smem: stage = A[128][64]h (16KB) + B[128][64]h (16KB); 3 stages = 96KB.
// Row layout: 128B/row = 8 chunks of 16B; chunk' = chunk ^ (row&7).
// ---------------------------------------------------------------------------
#define G2_STAGE 16384
#define G2_SMEM_BYTES (6 * G2_STAGE)     // 96 KB
#define NIT2 16                          // K / 64

__global__ __launch_bounds__(256) void gemm_fp16_cp3(
    const __half* __restrict__ A, const __half* __restrict__ Wbase,
    size_t wstride,
    const float* __restrict__ b0, const float* __restrict__ b1,
    const float* __restrict__ b2,
    float* __restrict__ C0, float* __restrict__ C1, float* __restrict__ C2,
    int M, int N, int K)
{
    extern __shared__ char gsm[];
    const int z = blockIdx.z;
    const __half* W   = Wbase + (size_t)z * wstride;
    const float* bias = (z == 0) ? b0 : (z == 1) ? b1 : b2;
    float*       C    = (z == 0) ? C0 : (z == 1) ? C1 : C2;

    const int tid    = threadIdx.x;
    const int warpId = tid >> 5;
    const int lane   = tid & 31;
    const int r      = lane >> 2;
    const int c      = lane & 3;
    const int warpM  = (warpId >> 2) * 64;
    const int warpN  = (warpId & 3) * 32;
    const int m0     = blockIdx.y * 128;
    const int n0     = blockIdx.x * 128;

    // loader: row = tid>>1 (0..127), half-row hc = tid&1 (32 halfs = 64B)
    const int gRow = tid >> 1;
    const int hc   = tid & 1;
    const __half* Ag = A + (size_t)(m0 + gRow) * K + hc * 32;
    const __half* Wg = W + (size_t)(n0 + gRow) * K + hc * 32;

    uint32_t soff[4];
#pragma unroll
    for (int j = 0; j < 4; ++j)
        soff[j] = (uint32_t)gRow * 128 +
                  ((uint32_t)((hc * 4 + j) ^ (gRow & 7)) << 4);

    uint32_t asb[3], bsb[3];
#pragma unroll
    for (int s = 0; s < 3; ++s) {
        asb[s] = smem_u32(gsm + s * G2_STAGE);
        bsb[s] = smem_u32(gsm + (3 + s) * G2_STAGE);
    }

    const int lrow8 = lane & 7;
    const int tsel  = lane >> 3;
    const int aRow  = warpM + ((tsel & 1) << 3) + lrow8;   // +16*mt
    const int aCa   = tsel >> 1;                           // k-chunk half
    const int bRow  = warpN + ((tsel >> 1) << 3) + lrow8;  // +16*p
    const int bCa   = tsel & 1;

    float acc[4][4][4];
#pragma unroll
    for (int mt = 0; mt < 4; ++mt)
#pragma unroll
        for (int nt = 0; nt < 4; ++nt)
#pragma unroll
            for (int q = 0; q < 4; ++q) acc[mt][nt][q] = 0.f;

    // prologue: stages 0,1
#pragma unroll
    for (int s = 0; s < 2; ++s) {
        const __half* An = Ag + s * 64;
        const __half* Wn = Wg + s * 64;
#pragma unroll
        for (int j = 0; j < 4; ++j) {
            CP_ASYNC16(asb[s] + soff[j], An + 8 * j);
            CP_ASYNC16(bsb[s] + soff[j], Wn + 8 * j);
        }
        CP_COMMIT();
    }

    int st = 0, sl = 2;
    for (int i = 0; i < NIT2; ++i) {
        CP_WAITG1();
        __syncthreads();

        if (i + 2 < NIT2) {
            const __half* An = Ag + (i + 2) * 64;
            const __half* Wn = Wg + (i + 2) * 64;
#pragma unroll
            for (int j = 0; j < 4; ++j) {
                CP_ASYNC16(asb[sl] + soff[j], An + 8 * j);
                CP_ASYNC16(bsb[sl] + soff[j], Wn + 8 * j);
            }
        }
        CP_COMMIT();

        const uint32_t a_s = asb[st], b_s = bsb[st];
#pragma unroll
        for (int ks = 0; ks < 4; ++ks) {   // each ks = k16
            uint32_t af[4][4];
            const uint32_t aChunk = (uint32_t)((2 * ks + aCa) ^ lrow8) << 4;
#pragma unroll
            for (int mt = 0; mt < 4; ++mt)
                ldsm_x4(a_s + ((uint32_t)(aRow + 16 * mt) << 7) + aChunk, af[mt]);

            uint32_t bf[2][4];
            const uint32_t bChunk = (uint32_t)((2 * ks + bCa) ^ lrow8) << 4;
#pragma unroll
            for (int p = 0; p < 2; ++p)
                ldsm_x4(b_s + ((uint32_t)(bRow + 16 * p) << 7) + bChunk, bf[p]);

#pragma unroll
            for (int nt = 0; nt < 4; ++nt) {
                const uint32_t bb0 = bf[nt >> 1][(nt & 1) << 1];
                const uint32_t bb1 = bf[nt >> 1][((nt & 1) << 1) + 1];
#pragma unroll
                for (int mt = 0; mt < 4; ++mt)
                    mma_fp16(acc[mt][nt], af[mt], bb0, bb1);
            }
        }
        st = (st == 2) ? 0 : st + 1;
        sl = (sl == 2) ? 0 : sl + 1;
    }

#pragma unroll
    for (int nt = 0; nt < 4; ++nt) {
        const int col = n0 + warpN + 8 * nt + 2 * c;
        const float2 bv = *(const float2*)&bias[col];
#pragma unroll
        for (int mt = 0; mt < 4; ++mt) {
            const int row = m0 + warpM + 16 * mt + r;
            float2 o0 = make_float2(acc[mt][nt][0] + bv.x, acc[mt][nt][1] + bv.y);
            float2 o1 = make_float2(acc[mt][nt][2] + bv.x, acc[mt][nt][3] + bv.y);
            *(float2*)&C[(size_t)row * N + col]       = o0;
            *(float2*)&C[(size_t)(row + 8) * N + col] = o1;
        }
    }
}

// ---------------------------------------------------------------------------
// Flash attention, bf16x2 (3-term split), m16n8k16 mma — round-8 version,
// except the output is written as fp16 (feeds the fp16 O-projection).
// ---------------------------------------------------------------------------
#define ATTN_SMEM_BYTES (6 * 64 * 128)   // 48 KB

__global__ __launch_bounds__(256) void attn_alibi_bf16(
    const float* __restrict__ Q, const float* __restrict__ K,
    const float* __restrict__ V, const unsigned char* __restrict__ pad,
    __half* __restrict__ O)
{
    const int qt = blockIdx.x;
    const int bh = blockIdx.y;
    const int b  = bh >> 4;
    const int h  = bh & 15;

    extern __shared__ char smc[];
    char* Qh = smc;
    char* Ql = Qh + 8192;
    char* Kh = Ql + 8192;    // also P hi
    char* Kl = Kh + 8192;    // also P lo
    char* Vh = Kl + 8192;
    char* Vl = Vh + 8192;

    __shared__ float red[64][2];
    __shared__ float m_s[64], l_s[64], sc_s[64], pads[64];

    const int tid  = threadIdx.x;
    const int warp = tid >> 5;
    const int lane = tid & 31;
    const int r    = lane >> 2;
    const int c    = lane & 3;
    const int wq   = warp >> 1;
    const int wk   = warp & 1;

    const int lrow8 = lane & 7;
    const int tsel  = lane >> 3;

    const int aRow = 16 * wq + ((tsel & 1) << 3) + lrow8;
    const int aCa  = tsel >> 1;
    const int aR7  = aRow & 7;
    const uint32_t qh_b = smem_u32(Qh) + (uint32_t)aRow * 128;
    const uint32_t ql_b = smem_u32(Ql) + (uint32_t)aRow * 128;
    const uint32_t ph_b = smem_u32(Kh) + (uint32_t)aRow * 128;
    const uint32_t pl_b = smem_u32(Kl) + (uint32_t)aRow * 128;

    const int kRow = 32 * wk + ((tsel >> 1) << 3) + lrow8;
    const int kCa  = tsel & 1;
    const int kR7  = kRow & 7;
    const uint32_t kh_b = smem_u32(Kh) + (uint32_t)kRow * 128;
    const uint32_t kl_b = smem_u32(Kl) + (uint32_t)kRow * 128;

    const int vRow = ((tsel & 1) << 3) + lrow8;
    const int vCa  = 4 * wk + (tsel >> 1);
    const int vR7  = vRow & 7;
    const uint32_t vh_b = smem_u32(Vh) + (uint32_t)vRow * 128;
    const uint32_t vl_b = smem_u32(Vl) + (uint32_t)vRow * 128;

    const float slope = exp2f(-0.5f * (float)(h + 1));

    const float* Qb = Q + ((size_t)b * SEQ_L) * D_MODEL + h * HEAD_DIM;
    const float* Kb = K + ((size_t)b * SEQ_L) * D_MODEL + h * HEAD_DIM;
    const float* Vb = V + ((size_t)b * SEQ_L) * D_MODEL + h * HEAD_DIM;
    const unsigned char* padb = pad + (size_t)b * SEQ_L;

    const int ldRow = tid >> 2;
    const int ldC0  = (tid & 3) * 2;
    const uint32_t off0 = (uint32_t)ldRow * 128 +
                          ((uint32_t)(ldC0 ^ (ldRow & 7)) << 4);
    const uint32_t off1 = (uint32_t)ldRow * 128 +
                          ((uint32_t)((ldC0 + 1) ^ (ldRow & 7)) << 4);
    const int ldD0 = (tid & 3) * 16;

    {
        const float* src = Qb + (size_t)(qt * 64 + ldRow) * D_MODEL + ldD0;
        uint32_t hw[8], lw[8];
#pragma unroll
        for (int j = 0; j < 4; ++j) {
            float4 v = *(const float4*)(src + 4 * j);
            split_pair(v.x * 0.125f, v.y * 0.125f, hw[2 * j], lw[2 * j]);
            split_pair(v.z * 0.125f, v.w * 0.125f, hw[2 * j + 1], lw[2 * j + 1]);
        }
        *(uint4*)(Qh + off0) = make_uint4(hw[0], hw[1], hw[2], hw[3]);
        *(uint4*)(Qh + off1) = make_uint4(hw[4], hw[5], hw[6], hw[7]);
        *(uint4*)(Ql + off0) = make_uint4(lw[0], lw[1], lw[2], lw[3]);
        *(uint4*)(Ql + off1) = make_uint4(lw[4], lw[5], lw[6], lw[7]);
    }
    if (tid < 64) { m_s[tid] = -1e30f; l_s[tid] = 0.f; }

    float Oacc[4][4];
#pragma unroll
    for (int nt = 0; nt < 4; ++nt)
#pragma unroll
        for (int q = 0; q < 4; ++q) Oacc[nt][q] = 0.f;

    const int row0 = 16 * wq + r;
    const int kt_lo = (qt >= 8) ? (qt - 8) : 0;

    for (int kt = kt_lo; kt <= qt; ++kt) {
        __syncthreads();
        {
            const float* ksrc = Kb + (size_t)(kt * 64 + ldRow) * D_MODEL + ldD0;
            const float* vsrc = Vb + (size_t)(kt * 64 + ldRow) * D_MODEL + ldD0;
            uint32_t hw[8], lw[8];
#pragma unroll
            for (int j = 0; j < 4; ++j) {
                float4 v = *(const float4*)(ksrc + 4 * j);
                split_pair(v.x, v.y, hw[2 * j], lw[2 * j]);
                split_pair(v.z, v.w, hw[2 * j + 1], lw[2 * j + 1]);
            }
            *(uint4*)(Kh + off0) = make_uint4(hw[0], hw[1], hw[2], hw[3]);
            *(uint4*)(Kh + off1) = make_uint4(hw[4], hw[5], hw[6], hw[7]);
            *(uint4*)(Kl + off0) = make_uint4(lw[0], lw[1], lw[2], lw[3]);
            *(uint4*)(Kl + off1) = make_uint4(lw[4], lw[5], lw[6], lw[7]);
#pragma unroll
            for (int j = 0; j < 4; ++j) {
                float4 v = *(const float4*)(vsrc + 4 * j);
                split_pair(v.x, v.y, hw[2 * j], lw[2 * j]);
                split_pair(v.z, v.w, hw[2 * j + 1], lw[2 * j + 1]);
            }
            *(uint4*)(Vh + off0) = make_uint4(hw[0], hw[1], hw[2], hw[3]);
            *(uint4*)(Vh + off1) = make_uint4(hw[4], hw[5], hw[6], hw[7]);
            *(uint4*)(Vl + off0) = make_uint4(lw[0], lw[1], lw[2], lw[3]);
            *(uint4*)(Vl + off1) = make_uint4(lw[4], lw[5], lw[6], lw[7]);
        }
        if (tid < 64) pads[tid] = padb[kt * 64 + tid] ? -1e30f : 0.f;
        __syncthreads();

        float Sacc[4][4];
#pragma unroll
        for (int nt = 0; nt < 4; ++nt)
#pragma unroll
            for (int q = 0; q < 4; ++q) Sacc[nt][q] = 0.f;

#pragma unroll
        for (int ks = 0; ks < 4; ++ks) {
            uint32_t ah[4], al[4];
            const uint32_t axo = ((uint32_t)((2 * ks + aCa) ^ aR7) << 4);
            ldsm_x4(qh_b + axo, ah);
            ldsm_x4(ql_b + axo, al);
            uint32_t bhf[2][4], blf[2][4];
            const uint32_t kxo = ((uint32_t)((2 * ks + kCa) ^ kR7) << 4);
#pragma unroll
            for (int p = 0; p < 2; ++p) {
                ldsm_x4(kh_b + (uint32_t)p * 2048 + kxo, bhf[p]);
                ldsm_x4(kl_b + (uint32_t)p * 2048 + kxo, blf[p]);
            }
#pragma unroll
            for (int nt = 0; nt < 4; ++nt) {
                const uint32_t bh0 = bhf[nt >> 1][(nt & 1) << 1];
                const uint32_t bh1 = bhf[nt >> 1][((nt & 1) << 1) + 1];
                const uint32_t bl0 = blf[nt >> 1][(nt & 1) << 1];
                const uint32_t bl1 = blf[nt >> 1][((nt & 1) << 1) + 1];
                mma_bf16(Sacc[nt], ah, bh0, bh1);
                mma_bf16(Sacc[nt], ah, bl0, bl1);
                mma_bf16(Sacc[nt], al, bh0, bh1);
            }
        }

        const int gi0 = qt * 64 + row0;
        const int gi1 = gi0 + 8;
        float mx0 = -1e30f, mx1 = -1e30f;
#pragma unroll
        for (int nt = 0; nt < 4; ++nt) {
            const int jl = 32 * wk + 8 * nt + 2 * c;
            const int gj0 = kt * 64 + jl, gj1 = gj0 + 1;
            const float pd0 = pads[jl], pd1 = pads[jl + 1];
            float s;
            s = Sacc[nt][0] + slope * (float)(gj0 - gi0) + pd0;
            if (gj0 > gi0 || gj0 < gi0 - WINDOW) s = -1e30f;
            Sacc[nt][0] = s; mx0 = fmaxf(mx0, s);
            s = Sacc[nt][1] + slope * (float)(gj1 - gi0) + pd1;
            if (gj1 > gi0 || gj1 < gi0 - WINDOW) s = -1e30f;
            Sacc[nt][1] = s; mx0 = fmaxf(mx0, s);
            s = Sacc[nt][2] + slope * (float)(gj0 - gi1) + pd0;
            if (gj0 > gi1 || gj0 < gi1 - WINDOW) s = -1e30f;
            Sacc[nt][2] = s; mx1 = fmaxf(mx1, s);
            s = Sacc[nt][3] + slope * (float)(gj1 - gi1) + pd1;
            if (gj1 > gi1 || gj1 < gi1 - WINDOW) s = -1e30f;
            Sacc[nt][3] = s; mx1 = fmaxf(mx1, s);
        }
        mx0 = fmaxf(mx0, __shfl_xor_sync(0xffffffffu, mx0, 1));
        mx0 = fmaxf(mx0, __shfl_xor_sync(0xffffffffu, mx0, 2));
        mx1 = fmaxf(mx1, __shfl_xor_sync(0xffffffffu, mx1, 1));
        mx1 = fmaxf(mx1, __shfl_xor_sync(0xffffffffu, mx1, 2));
        if (c == 0) { red[row0][wk] = mx0; red[row0 + 8][wk] = mx1; }
        __syncthreads();

        if (tid < 64) {
            const float mt = fmaxf(red[tid][0], red[tid][1]);
            const float mo = m_s[tid];
            const float mn = fmaxf(mo, mt);
            const float sc = __expf(mo - mn);
            m_s[tid] = mn; sc_s[tid] = sc; l_s[tid] *= sc;
        }
        __syncthreads();

        const float mn0 = m_s[row0], mn1 = m_s[row0 + 8];
        const float sc0 = sc_s[row0], sc1 = sc_s[row0 + 8];
        float rs0 = 0.f, rs1 = 0.f;
        const uint32_t prow0 = (uint32_t)row0 * 128;
        const uint32_t prow1 = (uint32_t)(row0 + 8) * 128;
        const uint32_t pxr = (uint32_t)(row0 & 7);
#pragma unroll
        for (int nt = 0; nt < 4; ++nt) {
            float p0 = (Sacc[nt][0] < -1e29f) ? 0.f : __expf(Sacc[nt][0] - mn0);
            float p1 = (Sacc[nt][1] < -1e29f) ? 0.f : __expf(Sacc[nt][1] - mn0);
            float p2 = (Sacc[nt][2] < -1e29f) ? 0.f : __expf(Sacc[nt][2] - mn1);
            float p3 = (Sacc[nt][3] < -1e29f) ? 0.f : __expf(Sacc[nt][3] - mn1);
            rs0 += p0 + p1; rs1 += p2 + p3;
            const uint32_t cxo = (((uint32_t)(4 * wk + nt) ^ pxr) << 4) + 4 * c;
            uint32_t ph, pl;
            split_pair(p0, p1, ph, pl);
            *(uint32_t*)(Kh + prow0 + cxo) = ph;
            *(uint32_t*)(Kl + prow0 + cxo) = pl;
            split_pair(p2, p3, ph, pl);
            *(uint32_t*)(Kh + prow1 + cxo) = ph;
            *(uint32_t*)(Kl + prow1 + cxo) = pl;
            Oacc[nt][0] *= sc0; Oacc[nt][1] *= sc0;
            Oacc[nt][2] *= sc1; Oacc[nt][3] *= sc1;
        }
        rs0 += __shfl_xor_sync(0xffffffffu, rs0, 1);
        rs0 += __shfl_xor_sync(0xffffffffu, rs0, 2);
        rs1 += __shfl_xor_sync(0xffffffffu, rs1, 1);
        rs1 += __shfl_xor_sync(0xffffffffu, rs1, 2);
        if (c == 0) { red[row0][wk] = rs0; red[row0 + 8][wk] = rs1; }
        __syncthreads();

        if (tid < 64) l_s[tid] += red[tid][0] + red[tid][1];

#pragma unroll
        for (int ks = 0; ks < 4; ++ks) {
            uint32_t ah[4], al[4];
            const uint32_t axo = ((uint32_t)((2 * ks + aCa) ^ aR7) << 4);
            ldsm_x4(ph_b + axo, ah);
            ldsm_x4(pl_b + axo, al);
            uint32_t bvh[2][4], bvl[2][4];
#pragma unroll
            for (int p = 0; p < 2; ++p) {
                const uint32_t vxo = (uint32_t)ks * 2048 +
                    (((uint32_t)(vCa + 2 * p) ^ vR7) << 4);
                ldsm_x4_t(vh_b + vxo, bvh[p]);
                ldsm_x4_t(vl_b + vxo, bvl[p]);
            }
#pragma unroll
            for (int nt = 0; nt < 4; ++nt) {
                const uint32_t bh0 = bvh[nt >> 1][(nt & 1) << 1];
                const uint32_t bh1 = bvh[nt >> 1][((nt & 1) << 1) + 1];
                const uint32_t bl0 = bvl[nt >> 1][(nt & 1) << 1];
                const uint32_t bl1 = bvl[nt >> 1][((nt & 1) << 1) + 1];
                mma_bf16(Oacc[nt], ah, bh0, bh1);
                mma_bf16(Oacc[nt], ah, bl0, bl1);
                mma_bf16(Oacc[nt], al, bh0, bh1);
            }
        }
    }
    __syncthreads();

    const float inv0 = 1.f / l_s[row0];
    const float inv1 = 1.f / l_s[row0 + 8];
    const int gi0 = qt * 64 + row0;
    __half* Ob = O + ((size_t)b * SEQ_L + gi0) * D_MODEL + h * HEAD_DIM;
#pragma unroll
    for (int nt = 0; nt < 4; ++nt) {
        const int dcol = 32 * wk + 8 * nt + 2 * c;
        __half2 o0 = __floats2half2_rn(Oacc[nt][0] * inv0, Oacc[nt][1] * inv0);
        __half2 o1 = __floats2half2_rn(Oacc[nt][2] * inv1, Oacc[nt][3] * inv1);
        *(__half2*)(Ob + dcol)               = o0;
        *(__half2*)(Ob + 8 * D_MODEL + dcol) = o1;
    }
}

// ---------------------------------------------------------------------------
extern "C" void kernel_launch(void* const* d_in, const int* in_sizes, int n_in,
                              void* d_out, int out_size)
{
    const float* x  = (const float*)d_in[0];
    const unsigned char* pad = (const unsigned char*)d_in[1];
    const float* Wq = (const float*)d_in[2];
    const float* bq = (const float*)d_in[3];
    const float* Wk = (const float*)d_in[4];
    const float* bk = (const float*)d_in[5];
    const float* Wv = (const float*)d_in[6];
    const float* bv = (const float*)d_in[7];
    const float* Wo = (const float*)d_in[8];
    const float* bo = (const float*)d_in[9];
    float* out = (float*)d_out;

    float *q, *k, *v;
    __half *att, *xh, *wh;
    cudaGetSymbolAddress((void**)&q,   g_q);
    cudaGetSymbolAddress((void**)&k,   g_k);
    cudaGetSymbolAddress((void**)&v,   g_v);
    cudaGetSymbolAddress((void**)&att, g_att);
    cudaGetSymbolAddress((void**)&xh,  g_xh);
    cudaGetSymbolAddress((void**)&wh,  g_wh);

    cudaFuncSetAttribute(gemm_fp16_cp3,
                         cudaFuncAttributeMaxDynamicSharedMemorySize,
                         G2_SMEM_BYTES);
    cudaFuncSetAttribute(attn_alibi_bf16,
                         cudaFuncAttributeMaxDynamicSharedMemorySize,
                         ATTN_SMEM_BYTES);

    const int WN  = D_MODEL * D_MODEL;         // 1M elts per weight
    const int xn4 = MTOT * D_MODEL / 4;        // 2M float4
    const int wn4 = WN / 4;                    // 256K float4
    dim3 rgrid((xn4 + 255) / 256, 5);
    round_fp16_multi<<<rgrid, 256>>>((const float4*)x, xh,
                                     (const float4*)Wq, (const float4*)Wk,
                                     (const float4*)Wv, (const float4*)Wo,
                                     wh, xn4, wn4);

    dim3 qkv_grid(D_MODEL / 128, MTOT / 128, 3); // (8, 64, 3)
    gemm_fp16_cp3<<<qkv_grid, 256, G2_SMEM_BYTES>>>(
        xh, wh, (size_t)WN, bq, bk, bv, q, k, v, MTOT, D_MODEL, D_MODEL);

    dim3 agrid(SEQ_L / 64, BATCH * N_HEADS);   // (32, 64)
    attn_alibi_bf16<<<agrid, 256, ATTN_SMEM_BYTES>>>(q, k, v, pad, att);

    dim3 o_grid(D_MODEL / 128, MTOT / 128, 1);
    gemm_fp16_cp3<<<o_grid, 256, G2_SMEM_BYTES>>>(
        att, wh + 3 * (size_t)WN, (size_t)0, bo, bo, bo, out, out, out,
        MTOT, D_MODEL, D_MODEL);
}

// round 12
// speedup vs baseline: 1.6739x; 1.1086x over previous
#include <cuda_runtime.h>
#include <cuda_bf16.h>
#include <cuda_fp16.h>
#include <cstdint>

#define D_MODEL  1024
#define N_HEADS  16
#define HEAD_DIM 64
#define SEQ_L    2048
#define BATCH    4
#define WINDOW   512

#define MTOT (BATCH * SEQ_L)          // 8192

__device__ __nv_bfloat16 g_qh[MTOT * D_MODEL];
__device__ __nv_bfloat16 g_ql[MTOT * D_MODEL];
__device__ __nv_bfloat16 g_kh[MTOT * D_MODEL];
__device__ __nv_bfloat16 g_kl[MTOT * D_MODEL];
__device__ __nv_bfloat16 g_vh[MTOT * D_MODEL];
__device__ __nv_bfloat16 g_vl[MTOT * D_MODEL];
__device__ __half        g_att[MTOT * D_MODEL];        // attention out (fp16)
__device__ __half        g_xh[MTOT * D_MODEL];         // fp16-rounded x
__device__ __half        g_wh[4 * D_MODEL * D_MODEL];  // fp16 Wq,Wk,Wv,Wo

__device__ __forceinline__ void mma_fp16(float* d, const uint32_t* a,
                                         uint32_t b0, uint32_t b1) {
    asm volatile(
        "mma.sync.aligned.m16n8k16.row.col.f32.f16.f16.f32 "
        "{%0,%1,%2,%3}, {%4,%5,%6,%7}, {%8,%9}, {%0,%1,%2,%3};"
        : "+f"(d[0]), "+f"(d[1]), "+f"(d[2]), "+f"(d[3])
        : "r"(a[0]), "r"(a[1]), "r"(a[2]), "r"(a[3]), "r"(b0), "r"(b1));
}
__device__ __forceinline__ void mma_bf16(float* d, const uint32_t* a,
                                         uint32_t b0, uint32_t b1) {
    asm volatile(
        "mma.sync.aligned.m16n8k16.row.col.f32.bf16.bf16.f32 "
        "{%0,%1,%2,%3}, {%4,%5,%6,%7}, {%8,%9}, {%0,%1,%2,%3};"
        : "+f"(d[0]), "+f"(d[1]), "+f"(d[2]), "+f"(d[3])
        : "r"(a[0]), "r"(a[1]), "r"(a[2]), "r"(a[3]), "r"(b0), "r"(b1));
}
__device__ __forceinline__ uint32_t smem_u32(const void* p) {
    uint32_t a;
    asm("{ .reg .u64 t; cvta.to.shared.u64 t, %1; cvt.u32.u64 %0, t; }"
        : "=r"(a) : "l"(p));
    return a;
}
__device__ __forceinline__ void ldsm_x4(uint32_t addr, uint32_t* r) {
    asm volatile(
        "ldmatrix.sync.aligned.m8n8.x4.shared.b16 {%0,%1,%2,%3}, [%4];"
        : "=r"(r[0]), "=r"(r[1]), "=r"(r[2]), "=r"(r[3]) : "r"(addr));
}
__device__ __forceinline__ void ldsm_x4_t(uint32_t addr, uint32_t* r) {
    asm volatile(
        "ldmatrix.sync.aligned.m8n8.x4.trans.shared.b16 {%0,%1,%2,%3}, [%4];"
        : "=r"(r[0]), "=r"(r[1]), "=r"(r[2]), "=r"(r[3]) : "r"(addr));
}
__device__ __forceinline__ void split_pair(float e0, float e1,
                                           uint32_t& h, uint32_t& l) {
    __nv_bfloat16 b0 = __float2bfloat16_rn(e0), b1 = __float2bfloat16_rn(e1);
    h = ((uint32_t)__bfloat16_as_ushort(b1) << 16) | __bfloat16_as_ushort(b0);
    float r0 = e0 - __bfloat162float(b0), r1 = e1 - __bfloat162float(b1);
    __nv_bfloat16 c0 = __float2bfloat16_rn(r0), c1 = __float2bfloat16_rn(r1);
    l = ((uint32_t)__bfloat16_as_ushort(c1) << 16) | __bfloat16_as_ushort(c0);
}

#define CP_ASYNC16(dst, src) \
    asm volatile("cp.async.cg.shared.global [%0], [%1], 16;" \
                 :: "r"(dst), "l"(src))
#define CP_COMMIT() asm volatile("cp.async.commit_group;")
#define CP_WAITG1() asm volatile("cp.async.wait_group 1;" ::: "memory")
#define CP_WAIT0()  asm volatile("cp.async.wait_group 0;" ::: "memory")

// ---------------------------------------------------------------------------
// Merged fp16 pre-round: y=0 -> x, y=1..4 -> Wq/Wk/Wv/Wo.
// ---------------------------------------------------------------------------
__global__ void round_fp16_multi(
    const float4* __restrict__ x,  __half* __restrict__ xh,
    const float4* __restrict__ wq, const float4* __restrict__ wk,
    const float4* __restrict__ wv, const float4* __restrict__ wo,
    __half* __restrict__ wh, int xn4, int wn4)
{
    const int y = blockIdx.y;
    const int i = blockIdx.x * blockDim.x + threadIdx.x;
    const float4* in;
    __half* out;
    int n4;
    if (y == 0)      { in = x;  out = xh;               n4 = xn4; }
    else if (y == 1) { in = wq; out = wh;               n4 = wn4; }
    else if (y == 2) { in = wk; out = wh + 4 * wn4;     n4 = wn4; }
    else if (y == 3) { in = wv; out = wh + 8 * wn4;     n4 = wn4; }
    else             { in = wo; out = wh + 12 * wn4;    n4 = wn4; }
    if (i < n4) {
        float4 v = in[i];
        __half2 h0 = __floats2half2_rn(v.x, v.y);
        __half2 h1 = __floats2half2_rn(v.z, v.w);
        *(uint2*)(out + 4 * i) =
            make_uint2(*(uint32_t*)&h0, *(uint32_t*)&h1);
    }
}

// ---------------------------------------------------------------------------
// fp16 GEMM, 3-stage cp.async, BK=64. SPLIT=true: write bf16 hi/lo planes
// (z==0 output additionally scaled by 0.125 for Q). SPLIT=false: fp32 C.
// ---------------------------------------------------------------------------
#define G2_STAGE 16384
#define G2_SMEM_BYTES (6 * G2_STAGE)     // 96 KB
#define NIT2 16                          // K / 64

template <bool SPLIT>
__global__ __launch_bounds__(256) void gemm_fp16_cp3(
    const __half* __restrict__ A, const __half* __restrict__ Wbase,
    size_t wstride,
    const float* __restrict__ b0, const float* __restrict__ b1,
    const float* __restrict__ b2,
    float* __restrict__ C0,
    __nv_bfloat16* __restrict__ H0, __nv_bfloat16* __restrict__ L0,
    __nv_bfloat16* __restrict__ H1, __nv_bfloat16* __restrict__ L1,
    __nv_bfloat16* __restrict__ H2, __nv_bfloat16* __restrict__ L2,
    int M, int N, int K)
{
    extern __shared__ char gsm[];
    const int z = blockIdx.z;
    const __half* W   = Wbase + (size_t)z * wstride;
    const float* bias = (z == 0) ? b0 : (z == 1) ? b1 : b2;

    const int tid    = threadIdx.x;
    const int warpId = tid >> 5;
    const int lane   = tid & 31;
    const int r      = lane >> 2;
    const int c      = lane & 3;
    const int warpM  = (warpId >> 2) * 64;
    const int warpN  = (warpId & 3) * 32;
    const int m0     = blockIdx.y * 128;
    const int n0     = blockIdx.x * 128;

    const int gRow = tid >> 1;
    const int hc   = tid & 1;
    const __half* Ag = A + (size_t)(m0 + gRow) * K + hc * 32;
    const __half* Wg = W + (size_t)(n0 + gRow) * K + hc * 32;

    uint32_t soff[4];
#pragma unroll
    for (int j = 0; j < 4; ++j)
        soff[j] = (uint32_t)gRow * 128 +
                  ((uint32_t)((hc * 4 + j) ^ (gRow & 7)) << 4);

    uint32_t asb[3], bsb[3];
#pragma unroll
    for (int s = 0; s < 3; ++s) {
        asb[s] = smem_u32(gsm + s * G2_STAGE);
        bsb[s] = smem_u32(gsm + (3 + s) * G2_STAGE);
    }

    const int lrow8 = lane & 7;
    const int tsel  = lane >> 3;
    const int aRow  = warpM + ((tsel & 1) << 3) + lrow8;
    const int aCa   = tsel >> 1;
    const int bRow  = warpN + ((tsel >> 1) << 3) + lrow8;
    const int bCa   = tsel & 1;

    float acc[4][4][4];
#pragma unroll
    for (int mt = 0; mt < 4; ++mt)
#pragma unroll
        for (int nt = 0; nt < 4; ++nt)
#pragma unroll
            for (int q = 0; q < 4; ++q) acc[mt][nt][q] = 0.f;

#pragma unroll
    for (int s = 0; s < 2; ++s) {
        const __half* An = Ag + s * 64;
        const __half* Wn = Wg + s * 64;
#pragma unroll
        for (int j = 0; j < 4; ++j) {
            CP_ASYNC16(asb[s] + soff[j], An + 8 * j);
            CP_ASYNC16(bsb[s] + soff[j], Wn + 8 * j);
        }
        CP_COMMIT();
    }

    int st = 0, sl = 2;
    for (int i = 0; i < NIT2; ++i) {
        CP_WAITG1();
        __syncthreads();

        if (i + 2 < NIT2) {
            const __half* An = Ag + (i + 2) * 64;
            const __half* Wn = Wg + (i + 2) * 64;
#pragma unroll
            for (int j = 0; j < 4; ++j) {
                CP_ASYNC16(asb[sl] + soff[j], An + 8 * j);
                CP_ASYNC16(bsb[sl] + soff[j], Wn + 8 * j);
            }
        }
        CP_COMMIT();

        const uint32_t a_s = asb[st], b_s = bsb[st];
#pragma unroll
        for (int ks = 0; ks < 4; ++ks) {
            uint32_t af[4][4];
            const uint32_t aChunk = (uint32_t)((2 * ks + aCa) ^ lrow8) << 4;
#pragma unroll
            for (int mt = 0; mt < 4; ++mt)
                ldsm_x4(a_s + ((uint32_t)(aRow + 16 * mt) << 7) + aChunk, af[mt]);

            uint32_t bf[2][4];
            const uint32_t bChunk = (uint32_t)((2 * ks + bCa) ^ lrow8) << 4;
#pragma unroll
            for (int p = 0; p < 2; ++p)
                ldsm_x4(b_s + ((uint32_t)(bRow + 16 * p) << 7) + bChunk, bf[p]);

#pragma unroll
            for (int nt = 0; nt < 4; ++nt) {
                const uint32_t bb0 = bf[nt >> 1][(nt & 1) << 1];
                const uint32_t bb1 = bf[nt >> 1][((nt & 1) << 1) + 1];
#pragma unroll
                for (int mt = 0; mt < 4; ++mt)
                    mma_fp16(acc[mt][nt], af[mt], bb0, bb1);
            }
        }
        st = (st == 2) ? 0 : st + 1;
        sl = (sl == 2) ? 0 : sl + 1;
    }

    if (SPLIT) {
        const float scl = (z == 0) ? 0.125f : 1.f;
        __nv_bfloat16* H = (z == 0) ? H0 : (z == 1) ? H1 : H2;
        __nv_bfloat16* L = (z == 0) ? L0 : (z == 1) ? L1 : L2;
#pragma unroll
        for (int nt = 0; nt < 4; ++nt) {
            const int col = n0 + warpN + 8 * nt + 2 * c;
            const float2 bv = *(const float2*)&bias[col];
#pragma unroll
            for (int mt = 0; mt < 4; ++mt) {
                const int row = m0 + warpM + 16 * mt + r;
                uint32_t hp, lp;
                split_pair((acc[mt][nt][0] + bv.x) * scl,
                           (acc[mt][nt][1] + bv.y) * scl, hp, lp);
                *(uint32_t*)&H[(size_t)row * N + col] = hp;
                *(uint32_t*)&L[(size_t)row * N + col] = lp;
                split_pair((acc[mt][nt][2] + bv.x) * scl,
                           (acc[mt][nt][3] + bv.y) * scl, hp, lp);
                *(uint32_t*)&H[(size_t)(row + 8) * N + col] = hp;
                *(uint32_t*)&L[(size_t)(row + 8) * N + col] = lp;
            }
        }
    } else {
#pragma unroll
        for (int nt = 0; nt < 4; ++nt) {
            const int col = n0 + warpN + 8 * nt + 2 * c;
            const float2 bv = *(const float2*)&bias[col];
#pragma unroll
            for (int mt = 0; mt < 4; ++mt) {
                const int row = m0 + warpM + 16 * mt + r;
                float2 o0 = make_float2(acc[mt][nt][0] + bv.x,
                                        acc[mt][nt][1] + bv.y);
                float2 o1 = make_float2(acc[mt][nt][2] + bv.x,
                                        acc[mt][nt][3] + bv.y);
                *(float2*)&C0[(size_t)row * N + col]       = o0;
                *(float2*)&C0[(size_t)(row + 8) * N + col] = o1;
            }
        }
    }
}

// ---------------------------------------------------------------------------
// Flash attention: bf16x2 planes loaded via cp.async (pre-split in GEMM),
// double-buffered K/V stages, load of tile kt+1 overlapped with compute.
// smem: Qh Ql Ph Pl (4x8KB) + 2 stages x (Kh Kl Vh Vl) (8x8KB) = 96 KB.
// ---------------------------------------------------------------------------
#define AQ_H 0
#define AQ_L 8192
#define AP_H 16384
#define AP_L 24576
#define AKV0 32768
#define AKV_STRIDE 32768
#define ATTN_SMEM_BYTES (96 * 1024)

__global__ __launch_bounds__(256) void attn_alibi_cp(
    const __nv_bfloat16* __restrict__ Qh_g, const __nv_bfloat16* __restrict__ Ql_g,
    const __nv_bfloat16* __restrict__ Kh_g, const __nv_bfloat16* __restrict__ Kl_g,
    const __nv_bfloat16* __restrict__ Vh_g, const __nv_bfloat16* __restrict__ Vl_g,
    const unsigned char* __restrict__ pad, __half* __restrict__ O)
{
    const int qt = blockIdx.x;
    const int bh = blockIdx.y;
    const int b  = bh >> 4;
    const int h  = bh & 15;

    extern __shared__ char smc[];
    const uint32_t smb = smem_u32(smc);

    __shared__ float red[64][2];
    __shared__ float m_s[64], l_s[64], sc_s[64];
    __shared__ float pads[2][64];

    const int tid  = threadIdx.x;
    const int warp = tid >> 5;
    const int lane = tid & 31;
    const int r    = lane >> 2;
    const int c    = lane & 3;
    const int wq   = warp >> 1;
    const int wk   = warp & 1;

    const int lrow8 = lane & 7;
    const int tsel  = lane >> 3;

    // A-frag geometry (Q and P)
    const int aRow = 16 * wq + ((tsel & 1) << 3) + lrow8;
    const int aCa  = tsel >> 1;
    const int aR7  = aRow & 7;
    const uint32_t qh_b = smb + AQ_H + (uint32_t)aRow * 128;
    const uint32_t ql_b = smb + AQ_L + (uint32_t)aRow * 128;
    const uint32_t ph_b = smb + AP_H + (uint32_t)aRow * 128;
    const uint32_t pl_b = smb + AP_L + (uint32_t)aRow * 128;

    // K B-frag geometry (offsets within a stage)
    const int kRow = 32 * wk + ((tsel >> 1) << 3) + lrow8;
    const int kCa  = tsel & 1;
    const int kR7  = kRow & 7;
    const uint32_t khRel = (uint32_t)kRow * 128;          // + stage base
    // V trans B-frag geometry
    const int vRow = ((tsel & 1) << 3) + lrow8;
    const int vCa  = 4 * wk + (tsel >> 1);
    const int vR7  = vRow & 7;
    const uint32_t vhRel = 16384u + (uint32_t)vRow * 128; // + stage base

    const float slope = exp2f(-0.5f * (float)(h + 1));
    const unsigned char* padb = pad + (size_t)b * SEQ_L;

    // loader geometry: row = tid>>2 (0..63), 16 bf16 from col (tid&3)*16
    const int ldRow = tid >> 2;
    const uint32_t off0 = (uint32_t)ldRow * 128 +
                          ((uint32_t)(((tid & 3) * 2) ^ (ldRow & 7)) << 4);
    const uint32_t off1 = (uint32_t)ldRow * 128 +
                          ((uint32_t)(((tid & 3) * 2 + 1) ^ (ldRow & 7)) << 4);
    const size_t gcol = (size_t)h * HEAD_DIM + (tid & 3) * 16;

    const int kt_lo = (qt >= 8) ? (qt - 8) : 0;

    // ---- prologue: Q tile + first K/V tile + pads ----
    {
        const size_t qidx = ((size_t)(b * SEQ_L + qt * 64 + ldRow)) * D_MODEL + gcol;
        CP_ASYNC16(smb + AQ_H + off0, Qh_g + qidx);
        CP_ASYNC16(smb + AQ_H + off1, Qh_g + qidx + 8);
        CP_ASYNC16(smb + AQ_L + off0, Ql_g + qidx);
        CP_ASYNC16(smb + AQ_L + off1, Ql_g + qidx + 8);
        const size_t kidx = ((size_t)(b * SEQ_L + kt_lo * 64 + ldRow)) * D_MODEL + gcol;
        const uint32_t s0 = smb + AKV0;
        CP_ASYNC16(s0 + off0,          Kh_g + kidx);
        CP_ASYNC16(s0 + off1,          Kh_g + kidx + 8);
        CP_ASYNC16(s0 + 8192 + off0,   Kl_g + kidx);
        CP_ASYNC16(s0 + 8192 + off1,   Kl_g + kidx + 8);
        CP_ASYNC16(s0 + 16384 + off0,  Vh_g + kidx);
        CP_ASYNC16(s0 + 16384 + off1,  Vh_g + kidx + 8);
        CP_ASYNC16(s0 + 24576 + off0,  Vl_g + kidx);
        CP_ASYNC16(s0 + 24576 + off1,  Vl_g + kidx + 8);
        CP_COMMIT();
    }
    if (tid < 64) {
        pads[kt_lo & 1][tid] = padb[kt_lo * 64 + tid] ? -1e30f : 0.f;
        m_s[tid] = -1e30f;
        l_s[tid] = 0.f;
    }

    float Oacc[4][4];
#pragma unroll
    for (int nt = 0; nt < 4; ++nt)
#pragma unroll
        for (int q = 0; q < 4; ++q) Oacc[nt][q] = 0.f;

    const int row0 = 16 * wq + r;

    int st = 0;
    for (int kt = kt_lo; kt <= qt; ++kt) {
        CP_WAIT0();
        __syncthreads();   // tile st ready+visible; stage st^1 fully consumed

        if (kt < qt) {     // issue next tile into stage st^1
            const size_t kidx =
                ((size_t)(b * SEQ_L + (kt + 1) * 64 + ldRow)) * D_MODEL + gcol;
            const uint32_t s1 = smb + AKV0 + (uint32_t)(st ^ 1) * AKV_STRIDE;
            CP_ASYNC16(s1 + off0,          Kh_g + kidx);
            CP_ASYNC16(s1 + off1,          Kh_g + kidx + 8);
            CP_ASYNC16(s1 + 8192 + off0,   Kl_g + kidx);
            CP_ASYNC16(s1 + 8192 + off1,   Kl_g + kidx + 8);
            CP_ASYNC16(s1 + 16384 + off0,  Vh_g + kidx);
            CP_ASYNC16(s1 + 16384 + off1,  Vh_g + kidx + 8);
            CP_ASYNC16(s1 + 24576 + off0,  Vl_g + kidx);
            CP_ASYNC16(s1 + 24576 + off1,  Vl_g + kidx + 8);
            CP_COMMIT();
            if (tid < 64)
                pads[(kt + 1) & 1][tid] = padb[(kt + 1) * 64 + tid] ? -1e30f : 0.f;
        }

        const uint32_t stb  = smb + AKV0 + (uint32_t)st * AKV_STRIDE;
        const uint32_t kh_b = stb + khRel;
        const uint32_t kl_b = kh_b + 8192;
        const uint32_t vh_b = stb + vhRel;
        const uint32_t vl_b = vh_b + 8192;
        const float* padc = pads[kt & 1];

        // ---- S = Q.K^T ----
        float Sacc[4][4];
#pragma unroll
        for (int nt = 0; nt < 4; ++nt)
#pragma unroll
            for (int q = 0; q < 4; ++q) Sacc[nt][q] = 0.f;

#pragma unroll
        for (int ks = 0; ks < 4; ++ks) {
            uint32_t ah[4], al[4];
            const uint32_t axo = ((uint32_t)((2 * ks + aCa) ^ aR7) << 4);
            ldsm_x4(qh_b + axo, ah);
            ldsm_x4(ql_b + axo, al);
            uint32_t bhf[2][4], blf[2][4];
            const uint32_t kxo = ((uint32_t)((2 * ks + kCa) ^ kR7) << 4);
#pragma unroll
            for (int p = 0; p < 2; ++p) {
                ldsm_x4(kh_b + (uint32_t)p * 2048 + kxo, bhf[p]);
                ldsm_x4(kl_b + (uint32_t)p * 2048 + kxo, blf[p]);
            }
#pragma unroll
            for (int nt = 0; nt < 4; ++nt) {
                const uint32_t bh0 = bhf[nt >> 1][(nt & 1) << 1];
                const uint32_t bh1 = bhf[nt >> 1][((nt & 1) << 1) + 1];
                const uint32_t bl0 = blf[nt >> 1][(nt & 1) << 1];
                const uint32_t bl1 = blf[nt >> 1][((nt & 1) << 1) + 1];
                mma_bf16(Sacc[nt], ah, bh0, bh1);
                mma_bf16(Sacc[nt], ah, bl0, bl1);
                mma_bf16(Sacc[nt], al, bh0, bh1);
            }
        }

        // ---- mask + ALiBi + row max ----
        const int gi0 = qt * 64 + row0;
        const int gi1 = gi0 + 8;
        float mx0 = -1e30f, mx1 = -1e30f;
#pragma unroll
        for (int nt = 0; nt < 4; ++nt) {
            const int jl = 32 * wk + 8 * nt + 2 * c;
            const int gj0 = kt * 64 + jl, gj1 = gj0 + 1;
            const float pd0 = padc[jl], pd1 = padc[jl + 1];
            float s;
            s = Sacc[nt][0] + slope * (float)(gj0 - gi0) + pd0;
            if (gj0 > gi0 || gj0 < gi0 - WINDOW) s = -1e30f;
            Sacc[nt][0] = s; mx0 = fmaxf(mx0, s);
            s = Sacc[nt][1] + slope * (float)(gj1 - gi0) + pd1;
            if (gj1 > gi0 || gj1 < gi0 - WINDOW) s = -1e30f;
            Sacc[nt][1] = s; mx0 = fmaxf(mx0, s);
            s = Sacc[nt][2] + slope * (float)(gj0 - gi1) + pd0;
            if (gj0 > gi1 || gj0 < gi1 - WINDOW) s = -1e30f;
            Sacc[nt][2] = s; mx1 = fmaxf(mx1, s);
            s = Sacc[nt][3] + slope * (float)(gj1 - gi1) + pd1;
            if (gj1 > gi1 || gj1 < gi1 - WINDOW) s = -1e30f;
            Sacc[nt][3] = s; mx1 = fmaxf(mx1, s);
        }
        mx0 = fmaxf(mx0, __shfl_xor_sync(0xffffffffu, mx0, 1));
        mx0 = fmaxf(mx0, __shfl_xor_sync(0xffffffffu, mx0, 2));
        mx1 = fmaxf(mx1, __shfl_xor_sync(0xffffffffu, mx1, 1));
        mx1 = fmaxf(mx1, __shfl_xor_sync(0xffffffffu, mx1, 2));
        if (c == 0) { red[row0][wk] = mx0; red[row0 + 8][wk] = mx1; }
        __syncthreads();

        if (tid < 64) {
            const float mt = fmaxf(red[tid][0], red[tid][1]);
            const float mo = m_s[tid];
            const float mn = fmaxf(mo, mt);
            const float sc = __expf(mo - mn);
            m_s[tid] = mn; sc_s[tid] = sc; l_s[tid] *= sc;
        }
        __syncthreads();

        // ---- P = exp(S-m); write bf16x2 P planes; rescale O ----
        const float mn0 = m_s[row0], mn1 = m_s[row0 + 8];
        const float sc0 = sc_s[row0], sc1 = sc_s[row0 + 8];
        float rs0 = 0.f, rs1 = 0.f;
        const uint32_t prow0 = (uint32_t)row0 * 128;
        const uint32_t prow1 = (uint32_t)(row0 + 8) * 128;
        const uint32_t pxr = (uint32_t)(row0 & 7);
#pragma unroll
        for (int nt = 0; nt < 4; ++nt) {
            float p0 = (Sacc[nt][0] < -1e29f) ? 0.f : __expf(Sacc[nt][0] - mn0);
            float p1 = (Sacc[nt][1] < -1e29f) ? 0.f : __expf(Sacc[nt][1] - mn0);
            float p2 = (Sacc[nt][2] < -1e29f) ? 0.f : __expf(Sacc[nt][2] - mn1);
            float p3 = (Sacc[nt][3] < -1e29f) ? 0.f : __expf(Sacc[nt][3] - mn1);
            rs0 += p0 + p1; rs1 += p2 + p3;
            const uint32_t cxo = (((uint32_t)(4 * wk + nt) ^ pxr) << 4) + 4 * c;
            uint32_t ph, pl;
            split_pair(p0, p1, ph, pl);
            *(uint32_t*)(smc + AP_H + prow0 + cxo) = ph;
            *(uint32_t*)(smc + AP_L + prow0 + cxo) = pl;
            split_pair(p2, p3, ph, pl);
            *(uint32_t*)(smc + AP_H + prow1 + cxo) = ph;
            *(uint32_t*)(smc + AP_L + prow1 + cxo) = pl;
            Oacc[nt][0] *= sc0; Oacc[nt][1] *= sc0;
            Oacc[nt][2] *= sc1; Oacc[nt][3] *= sc1;
        }
        rs0 += __shfl_xor_sync(0xffffffffu, rs0, 1);
        rs0 += __shfl_xor_sync(0xffffffffu, rs0, 2);
        rs1 += __shfl_xor_sync(0xffffffffu, rs1, 1);
        rs1 += __shfl_xor_sync(0xffffffffu, rs1, 2);
        if (c == 0) { red[row0][wk] = rs0; red[row0 + 8][wk] = rs1; }
        __syncthreads();

        if (tid < 64) l_s[tid] += red[tid][0] + red[tid][1];

        // ---- O += P.V ----
#pragma unroll
        for (int ks = 0; ks < 4; ++ks) {
            uint32_t ah[4], al[4];
            const uint32_t axo = ((uint32_t)((2 * ks + aCa) ^ aR7) << 4);
            ldsm_x4(ph_b + axo, ah);
            ldsm_x4(pl_b + axo, al);
            uint32_t bvh[2][4], bvl[2][4];
#pragma unroll
            for (int p = 0; p < 2; ++p) {
                const uint32_t vxo = (uint32_t)ks * 2048 +
                    (((uint32_t)(vCa + 2 * p) ^ vR7) << 4);
                ldsm_x4_t(vh_b + vxo, bvh[p]);
                ldsm_x4_t(vl_b + vxo, bvl[p]);
            }
#pragma unroll
            for (int nt = 0; nt < 4; ++nt) {
                const uint32_t bh0 = bvh[nt >> 1][(nt & 1) << 1];
                const uint32_t bh1 = bvh[nt >> 1][((nt & 1) << 1) + 1];
                const uint32_t bl0 = bvl[nt >> 1][(nt & 1) << 1];
                const uint32_t bl1 = bvl[nt >> 1][((nt & 1) << 1) + 1];
                mma_bf16(Oacc[nt], ah, bh0, bh1);
                mma_bf16(Oacc[nt], ah, bl0, bl1);
                mma_bf16(Oacc[nt], al, bh0, bh1);
            }
        }
        st ^= 1;
    }
    __syncthreads();

    const float inv0 = 1.f / l_s[row0];
    const float inv1 = 1.f / l_s[row0 + 8];
    const int gi0 = qt * 64 + row0;
    __half* Ob = O + ((size_t)b * SEQ_L + gi0) * D_MODEL + h * HEAD_DIM;
#pragma unroll
    for (int nt = 0; nt < 4; ++nt) {
        const int dcol = 32 * wk + 8 * nt + 2 * c;
        __half2 o0 = __floats2half2_rn(Oacc[nt][0] * inv0, Oacc[nt][1] * inv0);
        __half2 o1 = __floats2half2_rn(Oacc[nt][2] * inv1, Oacc[nt][3] * inv1);
        *(__half2*)(Ob + dcol)               = o0;
        *(__half2*)(Ob + 8 * D_MODEL + dcol) = o1;
    }
}

// ---------------------------------------------------------------------------
extern "C" void kernel_launch(void* const* d_in, const int* in_sizes, int n_in,
                              void* d_out, int out_size)
{
    const float* x  = (const float*)d_in[0];
    const unsigned char* pad = (const unsigned char*)d_in[1];
    const float* Wq = (const float*)d_in[2];
    const float* bq = (const float*)d_in[3];
    const float* Wk = (const float*)d_in[4];
    const float* bk = (const float*)d_in[5];
    const float* Wv = (const float*)d_in[6];
    const float* bv = (const float*)d_in[7];
    const float* Wo = (const float*)d_in[8];
    const float* bo = (const float*)d_in[9];
    float* out = (float*)d_out;

    __nv_bfloat16 *qh, *ql, *kh, *kl, *vh, *vl;
    __half *att, *xh, *wh;
    cudaGetSymbolAddress((void**)&qh,  g_qh);
    cudaGetSymbolAddress((void**)&ql,  g_ql);
    cudaGetSymbolAddress((void**)&kh,  g_kh);
    cudaGetSymbolAddress((void**)&kl,  g_kl);
    cudaGetSymbolAddress((void**)&vh,  g_vh);
    cudaGetSymbolAddress((void**)&vl,  g_vl);
    cudaGetSymbolAddress((void**)&att, g_att);
    cudaGetSymbolAddress((void**)&xh,  g_xh);
    cudaGetSymbolAddress((void**)&wh,  g_wh);

    cudaFuncSetAttribute(gemm_fp16_cp3<true>,
                         cudaFuncAttributeMaxDynamicSharedMemorySize,
                         G2_SMEM_BYTES);
    cudaFuncSetAttribute(gemm_fp16_cp3<false>,
                         cudaFuncAttributeMaxDynamicSharedMemorySize,
                         G2_SMEM_BYTES);
    cudaFuncSetAttribute(attn_alibi_cp,
                         cudaFuncAttributeMaxDynamicSharedMemorySize,
                         ATTN_SMEM_BYTES);

    const int WN  = D_MODEL * D_MODEL;
    const int xn4 = MTOT * D_MODEL / 4;
    const int wn4 = WN / 4;
    dim3 rgrid((xn4 + 255) / 256, 5);
    round_fp16_multi<<<rgrid, 256>>>((const float4*)x, xh,
                                     (const float4*)Wq, (const float4*)Wk,
                                     (const float4*)Wv, (const float4*)Wo,
                                     wh, xn4, wn4);

    dim3 qkv_grid(D_MODEL / 128, MTOT / 128, 3);
    gemm_fp16_cp3<true><<<qkv_grid, 256, G2_SMEM_BYTES>>>(
        xh, wh, (size_t)WN, bq, bk, bv, nullptr,
        qh, ql, kh, kl, vh, vl, MTOT, D_MODEL, D_MODEL);

    dim3 agrid(SEQ_L / 64, BATCH * N_HEADS);
    attn_alibi_cp<<<agrid, 256, ATTN_SMEM_BYTES>>>(
        qh, ql, kh, kl, vh, vl, pad, att);

    dim3 o_grid(D_MODEL / 128, MTOT / 128, 1);
    gemm_fp16_cp3<false><<<o_grid, 256, G2_SMEM_BYTES>>>(
        att, wh + 3 * (size_t)WN, (size_t)0, bo, bo, bo, out,
        nullptr, nullptr, nullptr, nullptr, nullptr, nullptr,
        MTOT, D_MODEL, D_MODEL);
}

// round 13
// speedup vs baseline: 1.7226x; 1.0291x over previous
#include <cuda_runtime.h>
#include <cuda_bf16.h>
#include <cuda_fp16.h>
#include <cstdint>

#define D_MODEL  1024
#define N_HEADS  16
#define HEAD_DIM 64
#define SEQ_L    2048
#define BATCH    4
#define WINDOW   512

#define MTOT (BATCH * SEQ_L)          // 8192

__device__ __nv_bfloat16 g_qh[MTOT * D_MODEL];
__device__ __nv_bfloat16 g_ql[MTOT * D_MODEL];
__device__ __nv_bfloat16 g_kh[MTOT * D_MODEL];
__device__ __nv_bfloat16 g_kl[MTOT * D_MODEL];
__device__ __nv_bfloat16 g_vh[MTOT * D_MODEL];
__device__ __nv_bfloat16 g_vl[MTOT * D_MODEL];
__device__ __half        g_att[MTOT * D_MODEL];        // attention out (fp16)
__device__ __half        g_xh[MTOT * D_MODEL];         // fp16-rounded x
__device__ __half        g_wh[4 * D_MODEL * D_MODEL];  // fp16 Wq,Wk,Wv,Wo

__device__ __forceinline__ void mma_fp16(float* d, const uint32_t* a,
                                         uint32_t b0, uint32_t b1) {
    asm volatile(
        "mma.sync.aligned.m16n8k16.row.col.f32.f16.f16.f32 "
        "{%0,%1,%2,%3}, {%4,%5,%6,%7}, {%8,%9}, {%0,%1,%2,%3};"
        : "+f"(d[0]), "+f"(d[1]), "+f"(d[2]), "+f"(d[3])
        : "r"(a[0]), "r"(a[1]), "r"(a[2]), "r"(a[3]), "r"(b0), "r"(b1));
}
__device__ __forceinline__ void mma_bf16(float* d, const uint32_t* a,
                                         uint32_t b0, uint32_t b1) {
    asm volatile(
        "mma.sync.aligned.m16n8k16.row.col.f32.bf16.bf16.f32 "
        "{%0,%1,%2,%3}, {%4,%5,%6,%7}, {%8,%9}, {%0,%1,%2,%3};"
        : "+f"(d[0]), "+f"(d[1]), "+f"(d[2]), "+f"(d[3])
        : "r"(a[0]), "r"(a[1]), "r"(a[2]), "r"(a[3]), "r"(b0), "r"(b1));
}
__device__ __forceinline__ uint32_t smem_u32(const void* p) {
    uint32_t a;
    asm("{ .reg .u64 t; cvta.to.shared.u64 t, %1; cvt.u32.u64 %0, t; }"
        : "=r"(a) : "l"(p));
    return a;
}
__device__ __forceinline__ void ldsm_x4(uint32_t addr, uint32_t* r) {
    asm volatile(
        "ldmatrix.sync.aligned.m8n8.x4.shared.b16 {%0,%1,%2,%3}, [%4];"
        : "=r"(r[0]), "=r"(r[1]), "=r"(r[2]), "=r"(r[3]) : "r"(addr));
}
__device__ __forceinline__ void ldsm_x4_t(uint32_t addr, uint32_t* r) {
    asm volatile(
        "ldmatrix.sync.aligned.m8n8.x4.trans.shared.b16 {%0,%1,%2,%3}, [%4];"
        : "=r"(r[0]), "=r"(r[1]), "=r"(r[2]), "=r"(r[3]) : "r"(addr));
}
__device__ __forceinline__ void split_pair(float e0, float e1,
                                           uint32_t& h, uint32_t& l) {
    __nv_bfloat16 b0 = __float2bfloat16_rn(e0), b1 = __float2bfloat16_rn(e1);
    h = ((uint32_t)__bfloat16_as_ushort(b1) << 16) | __bfloat16_as_ushort(b0);
    float r0 = e0 - __bfloat162float(b0), r1 = e1 - __bfloat162float(b1);
    __nv_bfloat16 c0 = __float2bfloat16_rn(r0), c1 = __float2bfloat16_rn(r1);
    l = ((uint32_t)__bfloat16_as_ushort(c1) << 16) | __bfloat16_as_ushort(c0);
}

#define CP_ASYNC16(dst, src) \
    asm volatile("cp.async.cg.shared.global [%0], [%1], 16;" \
                 :: "r"(dst), "l"(src))
#define CP_COMMIT() asm volatile("cp.async.commit_group;")
#define CP_WAITG1() asm volatile("cp.async.wait_group 1;" ::: "memory")
#define CP_WAIT0()  asm volatile("cp.async.wait_group 0;" ::: "memory")

// ---------------------------------------------------------------------------
// Merged fp16 pre-round: y=0 -> x, y=1..4 -> Wq/Wk/Wv/Wo.
// ---------------------------------------------------------------------------
__global__ void round_fp16_multi(
    const float4* __restrict__ x,  __half* __restrict__ xh,
    const float4* __restrict__ wq, const float4* __restrict__ wk,
    const float4* __restrict__ wv, const float4* __restrict__ wo,
    __half* __restrict__ wh, int xn4, int wn4)
{
    const int y = blockIdx.y;
    const int i = blockIdx.x * blockDim.x + threadIdx.x;
    const float4* in;
    __half* out;
    int n4;
    if (y == 0)      { in = x;  out = xh;               n4 = xn4; }
    else if (y == 1) { in = wq; out = wh;               n4 = wn4; }
    else if (y == 2) { in = wk; out = wh + 4 * wn4;     n4 = wn4; }
    else if (y == 3) { in = wv; out = wh + 8 * wn4;     n4 = wn4; }
    else             { in = wo; out = wh + 12 * wn4;    n4 = wn4; }
    if (i < n4) {
        float4 v = in[i];
        __half2 h0 = __floats2half2_rn(v.x, v.y);
        __half2 h1 = __floats2half2_rn(v.z, v.w);
        *(uint2*)(out + 4 * i) =
            make_uint2(*(uint32_t*)&h0, *(uint32_t*)&h1);
    }
}

// ---------------------------------------------------------------------------
// fp16 GEMM, 3-stage cp.async, BK=64. SPLIT=true: write bf16 hi/lo planes
// (z==0 output additionally scaled by 0.125 for Q). SPLIT=false: fp32 C.
// ---------------------------------------------------------------------------
#define G2_STAGE 16384
#define G2_SMEM_BYTES (6 * G2_STAGE)     // 96 KB
#define NIT2 16                          // K / 64

template <bool SPLIT>
__global__ __launch_bounds__(256) void gemm_fp16_cp3(
    const __half* __restrict__ A, const __half* __restrict__ Wbase,
    size_t wstride,
    const float* __restrict__ b0, const float* __restrict__ b1,
    const float* __restrict__ b2,
    float* __restrict__ C0,
    __nv_bfloat16* __restrict__ H0, __nv_bfloat16* __restrict__ L0,
    __nv_bfloat16* __restrict__ H1, __nv_bfloat16* __restrict__ L1,
    __nv_bfloat16* __restrict__ H2, __nv_bfloat16* __restrict__ L2,
    int M, int N, int K)
{
    extern __shared__ char gsm[];
    const int z = blockIdx.z;
    const __half* W   = Wbase + (size_t)z * wstride;
    const float* bias = (z == 0) ? b0 : (z == 1) ? b1 : b2;

    const int tid    = threadIdx.x;
    const int warpId = tid >> 5;
    const int lane   = tid & 31;
    const int r      = lane >> 2;
    const int c      = lane & 3;
    const int warpM  = (warpId >> 2) * 64;
    const int warpN  = (warpId & 3) * 32;
    const int m0     = blockIdx.y * 128;
    const int n0     = blockIdx.x * 128;

    const int gRow = tid >> 1;
    const int hc   = tid & 1;
    const __half* Ag = A + (size_t)(m0 + gRow) * K + hc * 32;
    const __half* Wg = W + (size_t)(n0 + gRow) * K + hc * 32;

    uint32_t soff[4];
#pragma unroll
    for (int j = 0; j < 4; ++j)
        soff[j] = (uint32_t)gRow * 128 +
                  ((uint32_t)((hc * 4 + j) ^ (gRow & 7)) << 4);

    uint32_t asb[3], bsb[3];
#pragma unroll
    for (int s = 0; s < 3; ++s) {
        asb[s] = smem_u32(gsm + s * G2_STAGE);
        bsb[s] = smem_u32(gsm + (3 + s) * G2_STAGE);
    }

    const int lrow8 = lane & 7;
    const int tsel  = lane >> 3;
    const int aRow  = warpM + ((tsel & 1) << 3) + lrow8;
    const int aCa   = tsel >> 1;
    const int bRow  = warpN + ((tsel >> 1) << 3) + lrow8;
    const int bCa   = tsel & 1;

    float acc[4][4][4];
#pragma unroll
    for (int mt = 0; mt < 4; ++mt)
#pragma unroll
        for (int nt = 0; nt < 4; ++nt)
#pragma unroll
            for (int q = 0; q < 4; ++q) acc[mt][nt][q] = 0.f;

#pragma unroll
    for (int s = 0; s < 2; ++s) {
        const __half* An = Ag + s * 64;
        const __half* Wn = Wg + s * 64;
#pragma unroll
        for (int j = 0; j < 4; ++j) {
            CP_ASYNC16(asb[s] + soff[j], An + 8 * j);
            CP_ASYNC16(bsb[s] + soff[j], Wn + 8 * j);
        }
        CP_COMMIT();
    }

    int st = 0, sl = 2;
    for (int i = 0; i < NIT2; ++i) {
        CP_WAITG1();
        __syncthreads();

        if (i + 2 < NIT2) {
            const __half* An = Ag + (i + 2) * 64;
            const __half* Wn = Wg + (i + 2) * 64;
#pragma unroll
            for (int j = 0; j < 4; ++j) {
                CP_ASYNC16(asb[sl] + soff[j], An + 8 * j);
                CP_ASYNC16(bsb[sl] + soff[j], Wn + 8 * j);
            }
        }
        CP_COMMIT();

        const uint32_t a_s = asb[st], b_s = bsb[st];
#pragma unroll
        for (int ks = 0; ks < 4; ++ks) {
            uint32_t af[4][4];
            const uint32_t aChunk = (uint32_t)((2 * ks + aCa) ^ lrow8) << 4;
#pragma unroll
            for (int mt = 0; mt < 4; ++mt)
                ldsm_x4(a_s + ((uint32_t)(aRow + 16 * mt) << 7) + aChunk, af[mt]);

            uint32_t bf[2][4];
            const uint32_t bChunk = (uint32_t)((2 * ks + bCa) ^ lrow8) << 4;
#pragma unroll
            for (int p = 0; p < 2; ++p)
                ldsm_x4(b_s + ((uint32_t)(bRow + 16 * p) << 7) + bChunk, bf[p]);

#pragma unroll
            for (int nt = 0; nt < 4; ++nt) {
                const uint32_t bb0 = bf[nt >> 1][(nt & 1) << 1];
                const uint32_t bb1 = bf[nt >> 1][((nt & 1) << 1) + 1];
#pragma unroll
                for (int mt = 0; mt < 4; ++mt)
                    mma_fp16(acc[mt][nt], af[mt], bb0, bb1);
            }
        }
        st = (st == 2) ? 0 : st + 1;
        sl = (sl == 2) ? 0 : sl + 1;
    }

    if (SPLIT) {
        const float scl = (z == 0) ? 0.125f : 1.f;
        __nv_bfloat16* H = (z == 0) ? H0 : (z == 1) ? H1 : H2;
        __nv_bfloat16* L = (z == 0) ? L0 : (z == 1) ? L1 : L2;
#pragma unroll
        for (int nt = 0; nt < 4; ++nt) {
            const int col = n0 + warpN + 8 * nt + 2 * c;
            const float2 bv = *(const float2*)&bias[col];
#pragma unroll
            for (int mt = 0; mt < 4; ++mt) {
                const int row = m0 + warpM + 16 * mt + r;
                uint32_t hp, lp;
                split_pair((acc[mt][nt][0] + bv.x) * scl,
                           (acc[mt][nt][1] + bv.y) * scl, hp, lp);
                *(uint32_t*)&H[(size_t)row * N + col] = hp;
                *(uint32_t*)&L[(size_t)row * N + col] = lp;
                split_pair((acc[mt][nt][2] + bv.x) * scl,
                           (acc[mt][nt][3] + bv.y) * scl, hp, lp);
                *(uint32_t*)&H[(size_t)(row + 8) * N + col] = hp;
                *(uint32_t*)&L[(size_t)(row + 8) * N + col] = lp;
            }
        }
    } else {
#pragma unroll
        for (int nt = 0; nt < 4; ++nt) {
            const int col = n0 + warpN + 8 * nt + 2 * c;
            const float2 bv = *(const float2*)&bias[col];
#pragma unroll
            for (int mt = 0; mt < 4; ++mt) {
                const int row = m0 + warpM + 16 * mt + r;
                float2 o0 = make_float2(acc[mt][nt][0] + bv.x,
                                        acc[mt][nt][1] + bv.y);
                float2 o1 = make_float2(acc[mt][nt][2] + bv.x,
                                        acc[mt][nt][3] + bv.y);
                *(float2*)&C0[(size_t)row * N + col]       = o0;
                *(float2*)&C0[(size_t)(row + 8) * N + col] = o1;
            }
        }
    }
}

// ---------------------------------------------------------------------------
// Flash attention: bf16x2 planes via cp.async, double-buffered K/V stages,
// registerized softmax state (m,l in registers), 3 barriers per key-tile.
// smem: Qh Ql Ph Pl (4x8KB) + 2 stages x (Kh Kl Vh Vl) (8x8KB) = 96 KB.
// ---------------------------------------------------------------------------
#define AQ_H 0
#define AQ_L 8192
#define AP_H 16384
#define AP_L 24576
#define AKV0 32768
#define AKV_STRIDE 32768
#define ATTN_SMEM_BYTES (96 * 1024)

__global__ __launch_bounds__(256, 2) void attn_alibi_cp(
    const __nv_bfloat16* __restrict__ Qh_g, const __nv_bfloat16* __restrict__ Ql_g,
    const __nv_bfloat16* __restrict__ Kh_g, const __nv_bfloat16* __restrict__ Kl_g,
    const __nv_bfloat16* __restrict__ Vh_g, const __nv_bfloat16* __restrict__ Vl_g,
    const unsigned char* __restrict__ pad, __half* __restrict__ O)
{
    const int qt = blockIdx.x;
    const int bh = blockIdx.y;
    const int b  = bh >> 4;
    const int h  = bh & 15;

    extern __shared__ char smc[];
    const uint32_t smb = smem_u32(smc);

    __shared__ float redA[64][2];   // max exchange
    __shared__ float redB[64][2];   // sum exchange
    __shared__ float pads[2][64];

    const int tid  = threadIdx.x;
    const int warp = tid >> 5;
    const int lane = tid & 31;
    const int r    = lane >> 2;
    const int c    = lane & 3;
    const int wq   = warp >> 1;
    const int wk   = warp & 1;

    const int lrow8 = lane & 7;
    const int tsel  = lane >> 3;

    // A-frag geometry (Q and P)
    const int aRow = 16 * wq + ((tsel & 1) << 3) + lrow8;
    const int aCa  = tsel >> 1;
    const int aR7  = aRow & 7;
    const uint32_t qh_b = smb + AQ_H + (uint32_t)aRow * 128;
    const uint32_t ql_b = smb + AQ_L + (uint32_t)aRow * 128;
    const uint32_t ph_b = smb + AP_H + (uint32_t)aRow * 128;
    const uint32_t pl_b = smb + AP_L + (uint32_t)aRow * 128;

    // K B-frag geometry (offsets within a stage)
    const int kRow = 32 * wk + ((tsel >> 1) << 3) + lrow8;
    const int kCa  = tsel & 1;
    const int kR7  = kRow & 7;
    const uint32_t khRel = (uint32_t)kRow * 128;
    // V trans B-frag geometry
    const int vRow = ((tsel & 1) << 3) + lrow8;
    const int vCa  = 4 * wk + (tsel >> 1);
    const int vR7  = vRow & 7;
    const uint32_t vhRel = 16384u + (uint32_t)vRow * 128;

    const float slope = exp2f(-0.5f * (float)(h + 1));
    const unsigned char* padb = pad + (size_t)b * SEQ_L;

    const int ldRow = tid >> 2;
    const uint32_t off0 = (uint32_t)ldRow * 128 +
                          ((uint32_t)(((tid & 3) * 2) ^ (ldRow & 7)) << 4);
    const uint32_t off1 = (uint32_t)ldRow * 128 +
                          ((uint32_t)(((tid & 3) * 2 + 1) ^ (ldRow & 7)) << 4);
    const size_t gcol = (size_t)h * HEAD_DIM + (tid & 3) * 16;

    const int kt_lo = (qt >= 8) ? (qt - 8) : 0;

    // ---- prologue: Q tile + first K/V tile + pads ----
    {
        const size_t qidx = ((size_t)(b * SEQ_L + qt * 64 + ldRow)) * D_MODEL + gcol;
        CP_ASYNC16(smb + AQ_H + off0, Qh_g + qidx);
        CP_ASYNC16(smb + AQ_H + off1, Qh_g + qidx + 8);
        CP_ASYNC16(smb + AQ_L + off0, Ql_g + qidx);
        CP_ASYNC16(smb + AQ_L + off1, Ql_g + qidx + 8);
        const size_t kidx = ((size_t)(b * SEQ_L + kt_lo * 64 + ldRow)) * D_MODEL + gcol;
        const uint32_t s0 = smb + AKV0;
        CP_ASYNC16(s0 + off0,          Kh_g + kidx);
        CP_ASYNC16(s0 + off1,          Kh_g + kidx + 8);
        CP_ASYNC16(s0 + 8192 + off0,   Kl_g + kidx);
        CP_ASYNC16(s0 + 8192 + off1,   Kl_g + kidx + 8);
        CP_ASYNC16(s0 + 16384 + off0,  Vh_g + kidx);
        CP_ASYNC16(s0 + 16384 + off1,  Vh_g + kidx + 8);
        CP_ASYNC16(s0 + 24576 + off0,  Vl_g + kidx);
        CP_ASYNC16(s0 + 24576 + off1,  Vl_g + kidx + 8);
        CP_COMMIT();
    }
    if (tid < 64)
        pads[kt_lo & 1][tid] = padb[kt_lo * 64 + tid] ? -1e30f : 0.f;

    float Oacc[4][4];
#pragma unroll
    for (int nt = 0; nt < 4; ++nt)
#pragma unroll
        for (int q = 0; q < 4; ++q) Oacc[nt][q] = 0.f;

    const int row0 = 16 * wq + r;
    // registerized softmax state (replicated across lanes sharing a row)
    float m0r = -1e30f, m1r = -1e30f, l0r = 0.f, l1r = 0.f;

    int st = 0;
    for (int kt = kt_lo; kt <= qt; ++kt) {
        CP_WAIT0();
        __syncthreads();   // B1: stage st ready; prior-iteration reads done

        if (kt < qt) {
            const size_t kidx =
                ((size_t)(b * SEQ_L + (kt + 1) * 64 + ldRow)) * D_MODEL + gcol;
            const uint32_t s1 = smb + AKV0 + (uint32_t)(st ^ 1) * AKV_STRIDE;
            CP_ASYNC16(s1 + off0,          Kh_g + kidx);
            CP_ASYNC16(s1 + off1,          Kh_g + kidx + 8);
            CP_ASYNC16(s1 + 8192 + off0,   Kl_g + kidx);
            CP_ASYNC16(s1 + 8192 + off1,   Kl_g + kidx + 8);
            CP_ASYNC16(s1 + 16384 + off0,  Vh_g + kidx);
            CP_ASYNC16(s1 + 16384 + off1,  Vh_g + kidx + 8);
            CP_ASYNC16(s1 + 24576 + off0,  Vl_g + kidx);
            CP_ASYNC16(s1 + 24576 + off1,  Vl_g + kidx + 8);
            CP_COMMIT();
            if (tid < 64)
                pads[(kt + 1) & 1][tid] = padb[(kt + 1) * 64 + tid] ? -1e30f : 0.f;
        }

        const uint32_t stb  = smb + AKV0 + (uint32_t)st * AKV_STRIDE;
        const uint32_t kh_b = stb + khRel;
        const uint32_t kl_b = kh_b + 8192;
        const uint32_t vh_b = stb + vhRel;
        const uint32_t vl_b = vh_b + 8192;
        const float* padc = pads[kt & 1];

        // ---- S = Q.K^T ----
        float Sacc[4][4];
#pragma unroll
        for (int nt = 0; nt < 4; ++nt)
#pragma unroll
            for (int q = 0; q < 4; ++q) Sacc[nt][q] = 0.f;

#pragma unroll
        for (int ks = 0; ks < 4; ++ks) {
            uint32_t ah[4], al[4];
            const uint32_t axo = ((uint32_t)((2 * ks + aCa) ^ aR7) << 4);
            ldsm_x4(qh_b + axo, ah);
            ldsm_x4(ql_b + axo, al);
            uint32_t bhf[2][4], blf[2][4];
            const uint32_t kxo = ((uint32_t)((2 * ks + kCa) ^ kR7) << 4);
#pragma unroll
            for (int p = 0; p < 2; ++p) {
                ldsm_x4(kh_b + (uint32_t)p * 2048 + kxo, bhf[p]);
                ldsm_x4(kl_b + (uint32_t)p * 2048 + kxo, blf[p]);
            }
#pragma unroll
            for (int nt = 0; nt < 4; ++nt) {
                const uint32_t bh0 = bhf[nt >> 1][(nt & 1) << 1];
                const uint32_t bh1 = bhf[nt >> 1][((nt & 1) << 1) + 1];
                const uint32_t bl0 = blf[nt >> 1][(nt & 1) << 1];
                const uint32_t bl1 = blf[nt >> 1][((nt & 1) << 1) + 1];
                mma_bf16(Sacc[nt], ah, bh0, bh1);
                mma_bf16(Sacc[nt], ah, bl0, bl1);
                mma_bf16(Sacc[nt], al, bh0, bh1);
            }
        }

        // ---- mask + ALiBi + row max ----
        const int gi0 = qt * 64 + row0;
        const int gi1 = gi0 + 8;
        float mx0 = -1e30f, mx1 = -1e30f;
#pragma unroll
        for (int nt = 0; nt < 4; ++nt) {
            const int jl = 32 * wk + 8 * nt + 2 * c;
            const int gj0 = kt * 64 + jl, gj1 = gj0 + 1;
            const float pd0 = padc[jl], pd1 = padc[jl + 1];
            float s;
            s = Sacc[nt][0] + slope * (float)(gj0 - gi0) + pd0;
            if (gj0 > gi0 || gj0 < gi0 - WINDOW) s = -1e30f;
            Sacc[nt][0] = s; mx0 = fmaxf(mx0, s);
            s = Sacc[nt][1] + slope * (float)(gj1 - gi0) + pd1;
            if (gj1 > gi0 || gj1 < gi0 - WINDOW) s = -1e30f;
            Sacc[nt][1] = s; mx0 = fmaxf(mx0, s);
            s = Sacc[nt][2] + slope * (float)(gj0 - gi1) + pd0;
            if (gj0 > gi1 || gj0 < gi1 - WINDOW) s = -1e30f;
            Sacc[nt][2] = s; mx1 = fmaxf(mx1, s);
            s = Sacc[nt][3] + slope * (float)(gj1 - gi1) + pd1;
            if (gj1 > gi1 || gj1 < gi1 - WINDOW) s = -1e30f;
            Sacc[nt][3] = s; mx1 = fmaxf(mx1, s);
        }
        mx0 = fmaxf(mx0, __shfl_xor_sync(0xffffffffu, mx0, 1));
        mx0 = fmaxf(mx0, __shfl_xor_sync(0xffffffffu, mx0, 2));
        mx1 = fmaxf(mx1, __shfl_xor_sync(0xffffffffu, mx1, 1));
        mx1 = fmaxf(mx1, __shfl_xor_sync(0xffffffffu, mx1, 2));
        if (c == 0) { redA[row0][wk] = mx0; redA[row0 + 8][wk] = mx1; }
        __syncthreads();   // B2: max exchange; fences K reads before P writes

        // ---- registerized m/l update (replicated per row owners) ----
        const float mt0 = fmaxf(redA[row0][0], redA[row0][1]);
        const float mt1 = fmaxf(redA[row0 + 8][0], redA[row0 + 8][1]);
        const float mn0 = fmaxf(m0r, mt0);
        const float mn1 = fmaxf(m1r, mt1);
        const float sc0 = __expf(m0r - mn0);
        const float sc1 = __expf(m1r - mn1);
        m0r = mn0; m1r = mn1;
        l0r *= sc0; l1r *= sc1;

        // ---- P = exp(S-m) (masked -> underflow 0); write P; rescale O ----
        float rs0 = 0.f, rs1 = 0.f;
        const uint32_t prow0 = (uint32_t)row0 * 128;
        const uint32_t prow1 = (uint32_t)(row0 + 8) * 128;
        const uint32_t pxr = (uint32_t)(row0 & 7);
#pragma unroll
        for (int nt = 0; nt < 4; ++nt) {
            float p0 = __expf(Sacc[nt][0] - mn0);
            float p1 = __expf(Sacc[nt][1] - mn0);
            float p2 = __expf(Sacc[nt][2] - mn1);
            float p3 = __expf(Sacc[nt][3] - mn1);
            rs0 += p0 + p1; rs1 += p2 + p3;
            const uint32_t cxo = (((uint32_t)(4 * wk + nt) ^ pxr) << 4) + 4 * c;
            uint32_t ph, pl;
            split_pair(p0, p1, ph, pl);
            *(uint32_t*)(smc + AP_H + prow0 + cxo) = ph;
            *(uint32_t*)(smc + AP_L + prow0 + cxo) = pl;
            split_pair(p2, p3, ph, pl);
            *(uint32_t*)(smc + AP_H + prow1 + cxo) = ph;
            *(uint32_t*)(smc + AP_L + prow1 + cxo) = pl;
            Oacc[nt][0] *= sc0; Oacc[nt][1] *= sc0;
            Oacc[nt][2] *= sc1; Oacc[nt][3] *= sc1;
        }
        rs0 += __shfl_xor_sync(0xffffffffu, rs0, 1);
        rs0 += __shfl_xor_sync(0xffffffffu, rs0, 2);
        rs1 += __shfl_xor_sync(0xffffffffu, rs1, 1);
        rs1 += __shfl_xor_sync(0xffffffffu, rs1, 2);
        if (c == 0) { redB[row0][wk] = rs0; redB[row0 + 8][wk] = rs1; }
        __syncthreads();   // B3: P visible + sum exchange

        l0r += redB[row0][0] + redB[row0][1];
        l1r += redB[row0 + 8][0] + redB[row0 + 8][1];

        // ---- O += P.V ----
#pragma unroll
        for (int ks = 0; ks < 4; ++ks) {
            uint32_t ah[4], al[4];
            const uint32_t axo = ((uint32_t)((2 * ks + aCa) ^ aR7) << 4);
            ldsm_x4(ph_b + axo, ah);
            ldsm_x4(pl_b + axo, al);
            uint32_t bvh[2][4], bvl[2][4];
#pragma unroll
            for (int p = 0; p < 2; ++p) {
                const uint32_t vxo = (uint32_t)ks * 2048 +
                    (((uint32_t)(vCa + 2 * p) ^ vR7) << 4);
                ldsm_x4_t(vh_b + vxo, bvh[p]);
                ldsm_x4_t(vl_b + vxo, bvl[p]);
            }
#pragma unroll
            for (int nt = 0; nt < 4; ++nt) {
                const uint32_t bh0 = bvh[nt >> 1][(nt & 1) << 1];
                const uint32_t bh1 = bvh[nt >> 1][((nt & 1) << 1) + 1];
                const uint32_t bl0 = bvl[nt >> 1][(nt & 1) << 1];
                const uint32_t bl1 = bvl[nt >> 1][((nt & 1) << 1) + 1];
                mma_bf16(Oacc[nt], ah, bh0, bh1);
                mma_bf16(Oacc[nt], ah, bl0, bl1);
                mma_bf16(Oacc[nt], al, bh0, bh1);
            }
        }
        st ^= 1;
    }

    const float inv0 = 1.f / l0r;
    const float inv1 = 1.f / l1r;
    const int gi0 = qt * 64 + row0;
    __half* Ob = O + ((size_t)b * SEQ_L + gi0) * D_MODEL + h * HEAD_DIM;
#pragma unroll
    for (int nt = 0; nt < 4; ++nt) {
        const int dcol = 32 * wk + 8 * nt + 2 * c;
        __half2 o0 = __floats2half2_rn(Oacc[nt][0] * inv0, Oacc[nt][1] * inv0);
        __half2 o1 = __floats2half2_rn(Oacc[nt][2] * inv1, Oacc[nt][3] * inv1);
        *(__half2*)(Ob + dcol)               = o0;
        *(__half2*)(Ob + 8 * D_MODEL + dcol) = o1;
    }
}

// ---------------------------------------------------------------------------
extern "C" void kernel_launch(void* const* d_in, const int* in_sizes, int n_in,
                              void* d_out, int out_size)
{
    const float* x  = (const float*)d_in[0];
    const unsigned char* pad = (const unsigned char*)d_in[1];
    const float* Wq = (const float*)d_in[2];
    const float* bq = (const float*)d_in[3];
    const float* Wk = (const float*)d_in[4];
    const float* bk = (const float*)d_in[5];
    const float* Wv = (const float*)d_in[6];
    const float* bv = (const float*)d_in[7];
    const float* Wo = (const float*)d_in[8];
    const float* bo = (const float*)d_in[9];
    float* out = (float*)d_out;

    __nv_bfloat16 *qh, *ql, *kh, *kl, *vh, *vl;
    __half *att, *xh, *wh;
    cudaGetSymbolAddress((void**)&qh,  g_qh);
    cudaGetSymbolAddress((void**)&ql,  g_ql);
    cudaGetSymbolAddress((void**)&kh,  g_kh);
    cudaGetSymbolAddress((void**)&kl,  g_kl);
    cudaGetSymbolAddress((void**)&vh,  g_vh);
    cudaGetSymbolAddress((void**)&vl,  g_vl);
    cudaGetSymbolAddress((void**)&att, g_att);
    cudaGetSymbolAddress((void**)&xh,  g_xh);
    cudaGetSymbolAddress((void**)&wh,  g_wh);

    cudaFuncSetAttribute(gemm_fp16_cp3<true>,
                         cudaFuncAttributeMaxDynamicSharedMemorySize,
                         G2_SMEM_BYTES);
    cudaFuncSetAttribute(gemm_fp16_cp3<false>,
                         cudaFuncAttributeMaxDynamicSharedMemorySize,
                         G2_SMEM_BYTES);
    cudaFuncSetAttribute(attn_alibi_cp,
                         cudaFuncAttributeMaxDynamicSharedMemorySize,
                         ATTN_SMEM_BYTES);

    const int WN  = D_MODEL * D_MODEL;
    const int xn4 = MTOT * D_MODEL / 4;
    const int wn4 = WN / 4;
    dim3 rgrid((xn4 + 255) / 256, 5);
    round_fp16_multi<<<rgrid, 256>>>((const float4*)x, xh,
                                     (const float4*)Wq, (const float4*)Wk,
                                     (const float4*)Wv, (const float4*)Wo,
                                     wh, xn4, wn4);

    dim3 qkv_grid(D_MODEL / 128, MTOT / 128, 3);
    gemm_fp16_cp3<true><<<qkv_grid, 256, G2_SMEM_BYTES>>>(
        xh, wh, (size_t)WN, bq, bk, bv, nullptr,
        qh, ql, kh, kl, vh, vl, MTOT, D_MODEL, D_MODEL);

    dim3 agrid(SEQ_L / 64, BATCH * N_HEADS);
    attn_alibi_cp<<<agrid, 256, ATTN_SMEM_BYTES>>>(
        qh, ql, kh, kl, vh, vl, pad, att);

    dim3 o_grid(D_MODEL / 128, MTOT / 128, 1);
    gemm_fp16_cp3<false><<<o_grid, 256, G2_SMEM_BYTES>>>(
        att, wh + 3 * (size_t)WN, (size_t)0, bo, bo, bo, out,
        nullptr, nullptr, nullptr, nullptr, nullptr, nullptr,
        MTOT, D_MODEL, D_MODEL);
}